// round 6
// baseline (speedup 1.0000x reference)
#include <cuda_runtime.h>

#define HID   128
#define INCH  271
#define SEQ   281
#define NCLS  1854
#define BATCH 256

typedef unsigned long long ull;

__device__ __forceinline__ ull pack2(float lo, float hi) {
    ull r; asm("mov.b64 %0, {%1,%2};" : "=l"(r) : "f"(lo), "f"(hi)); return r;
}
__device__ __forceinline__ void unpack2(ull v, float& lo, float& hi) {
    asm("mov.b64 {%0,%1}, %2;" : "=f"(lo), "=f"(hi) : "l"(v));
}
__device__ __forceinline__ ull fma2(ull a, ull b, ull c) {
    ull d; asm("fma.rn.f32x2 %0, %1, %2, %3;" : "=l"(d) : "l"(a), "l"(b), "l"(c)); return d;
}
__device__ __forceinline__ float sigmoidf_(float x) {
    return __fdividef(1.0f, 1.0f + __expf(-x));
}

// -------- device scratch (static, no allocations) --------
__device__ float4 g_G4[(size_t)SEQ * BATCH * 96];   // G[t][b][384] pre-activations
__device__ float4 g_Wq0ru[32 * 256];                // layer0 h-part r|u  (K=128,N=256)
__device__ float4 g_Wq0o [32 * 128];                // layer0 h-part o
__device__ float4 g_Wq1ru[64 * 256];                // layer1 r|u         (K=256,N=256)
__device__ float4 g_Wq1o [64 * 128];                // layer1 o
__device__ float  g_h1[BATCH * HID];                // final h1 [b][k]

// ============ 1. weight repack: [k][j] -> float4{[k4][j][kk]} ============
__global__ void pack_kernel(const float* __restrict__ Wr0, const float* __restrict__ Wu0,
                            const float* __restrict__ Wo0, const float* __restrict__ Wr1,
                            const float* __restrict__ Wu1, const float* __restrict__ Wo1)
{
    int i = blockIdx.x * blockDim.x + threadIdx.x;
    if (i < 32768) {
        int kk = i & 3, j = (i >> 2) & 255, k4 = i >> 10;
        const float* W = (j < 128) ? Wr0 : Wu0;
        ((float*)g_Wq0ru)[i] = W[(271 + k4 * 4 + kk) * 128 + (j & 127)];
    } else if (i < 49152) {
        int v = i - 32768, kk = v & 3, j = (v >> 2) & 127, k4 = v >> 9;
        ((float*)g_Wq0o)[v] = Wo0[(271 + k4 * 4 + kk) * 128 + j];
    } else if (i < 114688) {
        int v = i - 49152, kk = v & 3, j = (v >> 2) & 255, k4 = v >> 10;
        const float* W = (j < 128) ? Wr1 : Wu1;
        ((float*)g_Wq1ru)[v] = W[(k4 * 4 + kk) * 128 + (j & 127)];
    } else if (i < 147456) {
        int v = i - 114688, kk = v & 3, j = (v >> 2) & 127, k4 = v >> 9;
        ((float*)g_Wq1o)[v] = Wo1[(k4 * 4 + kk) * 128 + j];
    }
}

// ============ 2. G[t][b][j] = X[b,:,t] @ W0x[:,j] + bias ============
__global__ __launch_bounds__(256) void gemm_x_kernel(
    const float* __restrict__ X,
    const float* __restrict__ Wr0, const float* __restrict__ br0,
    const float* __restrict__ Wu0, const float* __restrict__ bu0,
    const float* __restrict__ Wo0, const float* __restrict__ bo0)
{
    __shared__ __align__(16) float Xs[16 * 64];
    __shared__ __align__(16) float Ws[16 * 64];
    const int tid = threadIdx.x;
    const int jg0 = blockIdx.x * 64;          // 0..320 over 384
    const int t0  = blockIdx.y * 64;          // 0..256 over 281
    const int bz  = blockIdx.z;
    const int g   = jg0 >> 7;
    const float* Wsrc = (g == 0) ? Wr0 : (g == 1) ? Wu0 : Wo0;
    const float* bsrc = (g == 0) ? br0 : (g == 1) ? bu0 : bo0;
    const int jj0 = jg0 & 127;
    const int lr = tid >> 6, lc = tid & 63;
    const int ty = tid >> 4, tx = tid & 15;

    ull acc[4][2];
    #pragma unroll
    for (int m = 0; m < 4; m++) { acc[m][0] = 0ull; acc[m][1] = 0ull; }
    const float* Xb = X + (size_t)bz * (INCH * SEQ);

    for (int c0 = 0; c0 < INCH; c0 += 16) {
        #pragma unroll
        for (int i = 0; i < 4; i++) {
            int r = lr + 4 * i, c = c0 + r;
            float xv = 0.f, wv = 0.f;
            if (c < INCH) {
                int tcol = t0 + lc;
                if (tcol < SEQ) xv = Xb[c * SEQ + tcol];
                wv = Wsrc[c * 128 + jj0 + lc];
            }
            Xs[r * 64 + lc] = xv;
            Ws[r * 64 + lc] = wv;
        }
        __syncthreads();
        #pragma unroll
        for (int k = 0; k < 16; k++) {
            float4 a4 = *(const float4*)&Xs[k * 64 + ty * 4];
            ulonglong2 wv = *(const ulonglong2*)&Ws[k * 64 + tx * 4];
            const float* af = (const float*)&a4;
            #pragma unroll
            for (int m = 0; m < 4; m++) {
                ull ap = pack2(af[m], af[m]);
                acc[m][0] = fma2(ap, wv.x, acc[m][0]);
                acc[m][1] = fma2(ap, wv.y, acc[m][1]);
            }
        }
        __syncthreads();
    }
    float b0v = bsrc[jj0 + tx * 4 + 0], b1v = bsrc[jj0 + tx * 4 + 1];
    float b2v = bsrc[jj0 + tx * 4 + 2], b3v = bsrc[jj0 + tx * 4 + 3];
    float* Gf = (float*)g_G4;
    #pragma unroll
    for (int m = 0; m < 4; m++) {
        int tt = t0 + ty * 4 + m;
        if (tt < SEQ) {
            float o0, o1, o2, o3;
            unpack2(acc[m][0], o0, o1); unpack2(acc[m][1], o2, o3);
            *(float4*)&Gf[((size_t)tt * BATCH + bz) * 384 + jg0 + tx * 4] =
                make_float4(o0 + b0v, o1 + b1v, o2 + b2v, o3 + b3v);
        }
    }
}

// ============ 3. recurrence: 64 blocks x 4 batch rows ============
__global__ __launch_bounds__(256) void rnn_kernel(
    const float* __restrict__ br1, const float* __restrict__ bu1,
    const float* __restrict__ bo1)
{
    __shared__ __align__(16) float hs0[HID * 4];
    __shared__ __align__(16) float hs1[HID * 4];
    __shared__ __align__(16) float rh [HID * 4];
    __shared__ __align__(16) float us [4 * HID];

    const int tid = threadIdx.x;
    const int b0  = blockIdx.x * 4;
    const int jp  = tid & 127;
    const int p   = tid >> 7;

    for (int i = tid; i < HID * 4; i += 256) { hs0[i] = 0.f; hs1[i] = 0.f; }
    __syncthreads();

    const float bias_ru = (tid < 128) ? br1[tid] : bu1[tid - 128];
    const float bias_o  = bo1[jp];
    const float* Gf = (const float*)g_G4;

    for (int t = 0; t < SEQ; t++) {
        const float* Gt = Gf + ((size_t)t * BATCH + b0) * 384;

        // ---- layer0 r,u: thread = col j (0..255), 4 batch rows ----
        float gx0 = Gt[0 * 384 + tid], gx1 = Gt[1 * 384 + tid];
        float gx2 = Gt[2 * 384 + tid], gx3 = Gt[3 * 384 + tid];
        ull a01 = 0ull, a23 = 0ull;
        #pragma unroll 8
        for (int k4 = 0; k4 < 32; k4++) {
            float4 w = g_Wq0ru[k4 * 256 + tid];
            const float* wf = (const float*)&w;
            #pragma unroll
            for (int kk = 0; kk < 4; kk++) {
                ulonglong2 hv = *(const ulonglong2*)&hs0[(k4 * 4 + kk) * 4];
                ull wp = pack2(wf[kk], wf[kk]);
                a01 = fma2(hv.x, wp, a01);
                a23 = fma2(hv.y, wp, a23);
            }
        }
        {
            float v0, v1, v2, v3;
            unpack2(a01, v0, v1); unpack2(a23, v2, v3);
            v0 = sigmoidf_(v0 + gx0); v1 = sigmoidf_(v1 + gx1);
            v2 = sigmoidf_(v2 + gx2); v3 = sigmoidf_(v3 + gx3);
            if (tid < 128) {
                float4 h = *(const float4*)&hs0[tid * 4];
                *(float4*)&rh[tid * 4] = make_float4(v0*h.x, v1*h.y, v2*h.z, v3*h.w);
            } else {
                int jj = tid - 128;
                us[jj] = v0; us[128 + jj] = v1; us[256 + jj] = v2; us[384 + jj] = v3;
            }
        }
        __syncthreads();

        // ---- layer0 o + h0 update: thread = (jp, batch-pair p) ----
        float go0 = Gt[(2*p + 0) * 384 + 256 + jp];
        float go1 = Gt[(2*p + 1) * 384 + 256 + jp];
        ull a = 0ull;
        #pragma unroll 8
        for (int k4 = 0; k4 < 32; k4++) {
            float4 w = g_Wq0o[k4 * 128 + jp];
            const float* wf = (const float*)&w;
            #pragma unroll
            for (int kk = 0; kk < 4; kk++)
                a = fma2(*(const ull*)&rh[(k4*4+kk)*4 + 2*p], pack2(wf[kk], wf[kk]), a);
        }
        {
            float o0, o1; unpack2(a, o0, o1);
            o0 = tanhf(o0 + go0); o1 = tanhf(o1 + go1);
            int bA = 2*p, bB = 2*p + 1;
            float u0 = us[bA*128 + jp], u1 = us[bB*128 + jp];
            float hA = hs0[jp*4 + bA], hB = hs0[jp*4 + bB];
            hs0[jp*4 + bA] = fmaf(u0, o0 - hA, hA);
            hs0[jp*4 + bB] = fmaf(u1, o1 - hB, hB);
        }
        __syncthreads();

        // ---- layer1 r,u: K=256 = [h0_new | h1] ----
        a01 = 0ull; a23 = 0ull;
        #pragma unroll 8
        for (int k4 = 0; k4 < 32; k4++) {
            float4 w = g_Wq1ru[k4 * 256 + tid];
            const float* wf = (const float*)&w;
            #pragma unroll
            for (int kk = 0; kk < 4; kk++) {
                ulonglong2 hv = *(const ulonglong2*)&hs0[(k4*4+kk)*4];
                ull wp = pack2(wf[kk], wf[kk]);
                a01 = fma2(hv.x, wp, a01); a23 = fma2(hv.y, wp, a23);
            }
        }
        #pragma unroll 8
        for (int k4 = 0; k4 < 32; k4++) {
            float4 w = g_Wq1ru[(k4 + 32) * 256 + tid];
            const float* wf = (const float*)&w;
            #pragma unroll
            for (int kk = 0; kk < 4; kk++) {
                ulonglong2 hv = *(const ulonglong2*)&hs1[(k4*4+kk)*4];
                ull wp = pack2(wf[kk], wf[kk]);
                a01 = fma2(hv.x, wp, a01); a23 = fma2(hv.y, wp, a23);
            }
        }
        {
            float v0, v1, v2, v3;
            unpack2(a01, v0, v1); unpack2(a23, v2, v3);
            v0 = sigmoidf_(v0 + bias_ru); v1 = sigmoidf_(v1 + bias_ru);
            v2 = sigmoidf_(v2 + bias_ru); v3 = sigmoidf_(v3 + bias_ru);
            if (tid < 128) {
                float4 h = *(const float4*)&hs1[tid * 4];
                *(float4*)&rh[tid * 4] = make_float4(v0*h.x, v1*h.y, v2*h.z, v3*h.w);
            } else {
                int jj = tid - 128;
                us[jj] = v0; us[128 + jj] = v1; us[256 + jj] = v2; us[384 + jj] = v3;
            }
        }
        __syncthreads();

        // ---- layer1 o + h1 update: K=256 = [h0_new | r1*h1] ----
        a = 0ull;
        #pragma unroll 8
        for (int k4 = 0; k4 < 32; k4++) {
            float4 w = g_Wq1o[k4 * 128 + jp];
            const float* wf = (const float*)&w;
            #pragma unroll
            for (int kk = 0; kk < 4; kk++)
                a = fma2(*(const ull*)&hs0[(k4*4+kk)*4 + 2*p], pack2(wf[kk], wf[kk]), a);
        }
        #pragma unroll 8
        for (int k4 = 0; k4 < 32; k4++) {
            float4 w = g_Wq1o[(k4 + 32) * 128 + jp];
            const float* wf = (const float*)&w;
            #pragma unroll
            for (int kk = 0; kk < 4; kk++)
                a = fma2(*(const ull*)&rh[(k4*4+kk)*4 + 2*p], pack2(wf[kk], wf[kk]), a);
        }
        {
            float o0, o1; unpack2(a, o0, o1);
            o0 = tanhf(o0 + bias_o); o1 = tanhf(o1 + bias_o);
            int bA = 2*p, bB = 2*p + 1;
            float u0 = us[bA*128 + jp], u1 = us[bB*128 + jp];
            float hA = hs1[jp*4 + bA], hB = hs1[jp*4 + bB];
            hs1[jp*4 + bA] = fmaf(u0, o0 - hA, hA);
            hs1[jp*4 + bB] = fmaf(u1, o1 - hB, hB);
        }
        __syncthreads();
    }
    for (int i = tid; i < 512; i += 256)
        g_h1[(b0 + (i & 3)) * 128 + (i >> 2)] = hs1[i];
}

// ============ 4. classifier: out = h1 @ Wfc + bfc ============
__global__ __launch_bounds__(256) void fc_kernel(
    const float* __restrict__ Wfc, const float* __restrict__ bfc, float* __restrict__ out)
{
    __shared__ float h[4 * 128];
    const int tid = threadIdx.x, b0 = blockIdx.x * 4;
    for (int i = tid; i < 512; i += 256) h[i] = g_h1[(b0 + (i >> 7)) * 128 + (i & 127)];
    __syncthreads();
    for (int n = tid; n < NCLS; n += 256) {
        float a0 = 0.f, a1 = 0.f, a2 = 0.f, a3 = 0.f;
        #pragma unroll 4
        for (int k = 0; k < 128; k++) {
            float w = Wfc[k * NCLS + n];
            a0 = fmaf(h[k], w, a0);       a1 = fmaf(h[128 + k], w, a1);
            a2 = fmaf(h[256 + k], w, a2); a3 = fmaf(h[384 + k], w, a3);
        }
        float bb = bfc[n];
        out[(b0 + 0) * NCLS + n] = a0 + bb;
        out[(b0 + 1) * NCLS + n] = a1 + bb;
        out[(b0 + 2) * NCLS + n] = a2 + bb;
        out[(b0 + 3) * NCLS + n] = a3 + bb;
    }
}

extern "C" void kernel_launch(void* const* d_in, const int* in_sizes, int n_in,
                              void* d_out, int out_size)
{
    const float* X   = (const float*)d_in[0];
    const float* Wr0 = (const float*)d_in[1];  const float* br0 = (const float*)d_in[2];
    const float* Wu0 = (const float*)d_in[3];  const float* bu0 = (const float*)d_in[4];
    const float* Wo0 = (const float*)d_in[5];  const float* bo0 = (const float*)d_in[6];
    const float* Wr1 = (const float*)d_in[7];  const float* br1 = (const float*)d_in[8];
    const float* Wu1 = (const float*)d_in[9];  const float* bu1 = (const float*)d_in[10];
    const float* Wo1 = (const float*)d_in[11]; const float* bo1 = (const float*)d_in[12];
    const float* Wfc = (const float*)d_in[13]; const float* bfc = (const float*)d_in[14];
    float* out = (float*)d_out;

    pack_kernel<<<(147456 + 255) / 256, 256>>>(Wr0, Wu0, Wo0, Wr1, Wu1, Wo1);
    gemm_x_kernel<<<dim3(6, 5, BATCH), 256>>>(X, Wr0, br0, Wu0, bu0, Wo0, bo0);
    rnn_kernel<<<64, 256>>>(br1, bu1, bo1);
    fc_kernel<<<64, 256>>>(Wfc, bfc, out);
}

// round 8
// speedup vs baseline: 1.2330x; 1.2330x over previous
#include <cuda_runtime.h>

#define HID   128
#define INCH  271
#define SEQ   281
#define NCLS  1854
#define BATCH 256

typedef unsigned long long ull;

__device__ __forceinline__ ull pack2(float lo, float hi) {
    ull r; asm("mov.b64 %0, {%1,%2};" : "=l"(r) : "f"(lo), "f"(hi)); return r;
}
__device__ __forceinline__ void unpack2(ull v, float& lo, float& hi) {
    asm("mov.b64 {%0,%1}, %2;" : "=f"(lo), "=f"(hi) : "l"(v));
}
__device__ __forceinline__ ull fma2(ull a, ull b, ull c) {
    ull d; asm("fma.rn.f32x2 %0, %1, %2, %3;" : "=l"(d) : "l"(a), "l"(b), "l"(c)); return d;
}
__device__ __forceinline__ float sigmoidf_(float x) {
    return __fdividef(1.0f, 1.0f + __expf(-x));
}

// -------- device scratch (static, no allocations) --------
__device__ float4 g_G4[(size_t)SEQ * BATCH * 96];   // G[t][b][384] pre-activations
__device__ float4 g_Wq0ru[32 * 256];                // layer0 h-part r|u  (K=128,N=256)
__device__ float4 g_Wq0o [32 * 128];                // layer0 h-part o
__device__ float4 g_Wq1ru[64 * 256];                // layer1 r|u         (K=256,N=256)
__device__ float4 g_Wq1o [64 * 128];                // layer1 o
__device__ float  g_h1[BATCH * HID];                // final h1 [b][k]

// ============ 1. weight repack: [k][j] -> float4{[k4][j][kk]} ============
__global__ void pack_kernel(const float* __restrict__ Wr0, const float* __restrict__ Wu0,
                            const float* __restrict__ Wo0, const float* __restrict__ Wr1,
                            const float* __restrict__ Wu1, const float* __restrict__ Wo1)
{
    int i = blockIdx.x * blockDim.x + threadIdx.x;
    if (i < 32768) {
        int kk = i & 3, j = (i >> 2) & 255, k4 = i >> 10;
        const float* W = (j < 128) ? Wr0 : Wu0;
        ((float*)g_Wq0ru)[i] = W[(271 + k4 * 4 + kk) * 128 + (j & 127)];
    } else if (i < 49152) {
        int v = i - 32768, kk = v & 3, j = (v >> 2) & 127, k4 = v >> 9;
        ((float*)g_Wq0o)[v] = Wo0[(271 + k4 * 4 + kk) * 128 + j];
    } else if (i < 114688) {
        int v = i - 49152, kk = v & 3, j = (v >> 2) & 255, k4 = v >> 10;
        const float* W = (j < 128) ? Wr1 : Wu1;
        ((float*)g_Wq1ru)[v] = W[(k4 * 4 + kk) * 128 + (j & 127)];
    } else if (i < 147456) {
        int v = i - 114688, kk = v & 3, j = (v >> 2) & 127, k4 = v >> 9;
        ((float*)g_Wq1o)[v] = Wo1[(k4 * 4 + kk) * 128 + j];
    }
}

// ============ 2. G[t][b][j] = X[b,:,t] @ W0x[:,j] + bias ============
__global__ __launch_bounds__(256) void gemm_x_kernel(
    const float* __restrict__ X,
    const float* __restrict__ Wr0, const float* __restrict__ br0,
    const float* __restrict__ Wu0, const float* __restrict__ bu0,
    const float* __restrict__ Wo0, const float* __restrict__ bo0)
{
    __shared__ __align__(16) float Xs[16 * 64];
    __shared__ __align__(16) float Ws[16 * 64];
    const int tid = threadIdx.x;
    const int jg0 = blockIdx.x * 64;
    const int t0  = blockIdx.y * 64;
    const int bz  = blockIdx.z;
    const int g   = jg0 >> 7;
    const float* Wsrc = (g == 0) ? Wr0 : (g == 1) ? Wu0 : Wo0;
    const float* bsrc = (g == 0) ? br0 : (g == 1) ? bu0 : bo0;
    const int jj0 = jg0 & 127;
    const int lr = tid >> 6, lc = tid & 63;
    const int ty = tid >> 4, tx = tid & 15;

    ull acc[4][2];
    #pragma unroll
    for (int m = 0; m < 4; m++) { acc[m][0] = 0ull; acc[m][1] = 0ull; }
    const float* Xb = X + (size_t)bz * (INCH * SEQ);

    for (int c0 = 0; c0 < INCH; c0 += 16) {
        #pragma unroll
        for (int i = 0; i < 4; i++) {
            int r = lr + 4 * i, c = c0 + r;
            float xv = 0.f, wv = 0.f;
            if (c < INCH) {
                int tcol = t0 + lc;
                if (tcol < SEQ) xv = Xb[c * SEQ + tcol];
                wv = Wsrc[c * 128 + jj0 + lc];
            }
            Xs[r * 64 + lc] = xv;
            Ws[r * 64 + lc] = wv;
        }
        __syncthreads();
        #pragma unroll
        for (int k = 0; k < 16; k++) {
            float4 a4 = *(const float4*)&Xs[k * 64 + ty * 4];
            ulonglong2 wv = *(const ulonglong2*)&Ws[k * 64 + tx * 4];
            const float* af = (const float*)&a4;
            #pragma unroll
            for (int m = 0; m < 4; m++) {
                ull ap = pack2(af[m], af[m]);
                acc[m][0] = fma2(ap, wv.x, acc[m][0]);
                acc[m][1] = fma2(ap, wv.y, acc[m][1]);
            }
        }
        __syncthreads();
    }
    float b0v = bsrc[jj0 + tx * 4 + 0], b1v = bsrc[jj0 + tx * 4 + 1];
    float b2v = bsrc[jj0 + tx * 4 + 2], b3v = bsrc[jj0 + tx * 4 + 3];
    float* Gf = (float*)g_G4;
    #pragma unroll
    for (int m = 0; m < 4; m++) {
        int tt = t0 + ty * 4 + m;
        if (tt < SEQ) {
            float o0, o1, o2, o3;
            unpack2(acc[m][0], o0, o1); unpack2(acc[m][1], o2, o3);
            *(float4*)&Gf[((size_t)tt * BATCH + bz) * 384 + jg0 + tx * 4] =
                make_float4(o0 + b0v, o1 + b1v, o2 + b2v, o3 + b3v);
        }
    }
}

// ============ 3. recurrence: 64 blocks x 4 batch rows ============
// Layer-0 weights (192KB) resident in dynamic SMEM; layer-1 streamed from L2.
__global__ __launch_bounds__(256) void rnn_kernel(
    const float* __restrict__ br1, const float* __restrict__ bu1,
    const float* __restrict__ bo1)
{
    extern __shared__ __align__(16) float4 sW[];   // [0,8192) W0ru, [8192,12288) W0o
    __shared__ __align__(16) float hs0[HID * 4];
    __shared__ __align__(16) float hs1[HID * 4];
    __shared__ __align__(16) float rh [HID * 4];
    __shared__ __align__(16) float us [4 * HID];

    const int tid = threadIdx.x;
    const int b0  = blockIdx.x * 4;
    const int jp  = tid & 127;
    const int p   = tid >> 7;

    for (int i = tid; i < 12288; i += 256)
        sW[i] = (i < 8192) ? g_Wq0ru[i] : g_Wq0o[i - 8192];
    for (int i = tid; i < HID * 4; i += 256) { hs0[i] = 0.f; hs1[i] = 0.f; }
    __syncthreads();

    const float bias_ru = (tid < 128) ? br1[tid] : bu1[tid - 128];
    const float bias_o  = bo1[jp];
    const float* Gf = (const float*)g_G4;
    const float4* sW0o = sW + 8192;

    for (int t = 0; t < SEQ; t++) {
        const float* Gt = Gf + ((size_t)t * BATCH + b0) * 384;

        // ---- layer0 r,u (SMEM weights): thread = col j, 4 batch rows ----
        float gx0 = Gt[0 * 384 + tid], gx1 = Gt[1 * 384 + tid];
        float gx2 = Gt[2 * 384 + tid], gx3 = Gt[3 * 384 + tid];
        ull a01 = 0ull, a23 = 0ull;
        #pragma unroll 8
        for (int k4 = 0; k4 < 32; k4++) {
            float4 w = sW[k4 * 256 + tid];
            const float* wf = (const float*)&w;
            #pragma unroll
            for (int kk = 0; kk < 4; kk++) {
                ulonglong2 hv = *(const ulonglong2*)&hs0[(k4 * 4 + kk) * 4];
                ull wp = pack2(wf[kk], wf[kk]);
                a01 = fma2(hv.x, wp, a01);
                a23 = fma2(hv.y, wp, a23);
            }
        }
        {
            float v0, v1, v2, v3;
            unpack2(a01, v0, v1); unpack2(a23, v2, v3);
            v0 = sigmoidf_(v0 + gx0); v1 = sigmoidf_(v1 + gx1);
            v2 = sigmoidf_(v2 + gx2); v3 = sigmoidf_(v3 + gx3);
            if (tid < 128) {
                float4 h = *(const float4*)&hs0[tid * 4];
                *(float4*)&rh[tid * 4] = make_float4(v0*h.x, v1*h.y, v2*h.z, v3*h.w);
            } else {
                int jj = tid - 128;
                us[jj] = v0; us[128 + jj] = v1; us[256 + jj] = v2; us[384 + jj] = v3;
            }
        }
        __syncthreads();

        // ---- layer0 o + h0 update (SMEM weights): thread = (jp, batch-pair p) ----
        float go0 = Gt[(2*p + 0) * 384 + 256 + jp];
        float go1 = Gt[(2*p + 1) * 384 + 256 + jp];
        ull a = 0ull;
        #pragma unroll 8
        for (int k4 = 0; k4 < 32; k4++) {
            float4 w = sW0o[k4 * 128 + jp];
            const float* wf = (const float*)&w;
            #pragma unroll
            for (int kk = 0; kk < 4; kk++)
                a = fma2(*(const ull*)&rh[(k4*4+kk)*4 + 2*p], pack2(wf[kk], wf[kk]), a);
        }
        {
            float o0, o1; unpack2(a, o0, o1);
            o0 = tanhf(o0 + go0); o1 = tanhf(o1 + go1);
            int bA = 2*p, bB = 2*p + 1;
            float u0 = us[bA*128 + jp], u1 = us[bB*128 + jp];
            float hA = hs0[jp*4 + bA], hB = hs0[jp*4 + bB];
            hs0[jp*4 + bA] = fmaf(u0, o0 - hA, hA);
            hs0[jp*4 + bB] = fmaf(u1, o1 - hB, hB);
        }
        __syncthreads();

        // ---- layer1 r,u (L2 weights): K=256 = [h0_new | h1] ----
        a01 = 0ull; a23 = 0ull;
        #pragma unroll 8
        for (int k4 = 0; k4 < 32; k4++) {
            float4 w = g_Wq1ru[k4 * 256 + tid];
            const float* wf = (const float*)&w;
            #pragma unroll
            for (int kk = 0; kk < 4; kk++) {
                ulonglong2 hv = *(const ulonglong2*)&hs0[(k4*4+kk)*4];
                ull wp = pack2(wf[kk], wf[kk]);
                a01 = fma2(hv.x, wp, a01); a23 = fma2(hv.y, wp, a23);
            }
        }
        #pragma unroll 8
        for (int k4 = 0; k4 < 32; k4++) {
            float4 w = g_Wq1ru[(k4 + 32) * 256 + tid];
            const float* wf = (const float*)&w;
            #pragma unroll
            for (int kk = 0; kk < 4; kk++) {
                ulonglong2 hv = *(const ulonglong2*)&hs1[(k4*4+kk)*4];
                ull wp = pack2(wf[kk], wf[kk]);
                a01 = fma2(hv.x, wp, a01); a23 = fma2(hv.y, wp, a23);
            }
        }
        {
            float v0, v1, v2, v3;
            unpack2(a01, v0, v1); unpack2(a23, v2, v3);
            v0 = sigmoidf_(v0 + bias_ru); v1 = sigmoidf_(v1 + bias_ru);
            v2 = sigmoidf_(v2 + bias_ru); v3 = sigmoidf_(v3 + bias_ru);
            if (tid < 128) {
                float4 h = *(const float4*)&hs1[tid * 4];
                *(float4*)&rh[tid * 4] = make_float4(v0*h.x, v1*h.y, v2*h.z, v3*h.w);
            } else {
                int jj = tid - 128;
                us[jj] = v0; us[128 + jj] = v1; us[256 + jj] = v2; us[384 + jj] = v3;
            }
        }
        __syncthreads();

        // ---- layer1 o + h1 update (L2 weights): K=256 = [h0_new | r1*h1] ----
        a = 0ull;
        #pragma unroll 8
        for (int k4 = 0; k4 < 32; k4++) {
            float4 w = g_Wq1o[k4 * 128 + jp];
            const float* wf = (const float*)&w;
            #pragma unroll
            for (int kk = 0; kk < 4; kk++)
                a = fma2(*(const ull*)&hs0[(k4*4+kk)*4 + 2*p], pack2(wf[kk], wf[kk]), a);
        }
        #pragma unroll 8
        for (int k4 = 0; k4 < 32; k4++) {
            float4 w = g_Wq1o[(k4 + 32) * 128 + jp];
            const float* wf = (const float*)&w;
            #pragma unroll
            for (int kk = 0; kk < 4; kk++)
                a = fma2(*(const ull*)&rh[(k4*4+kk)*4 + 2*p], pack2(wf[kk], wf[kk]), a);
        }
        {
            float o0, o1; unpack2(a, o0, o1);
            o0 = tanhf(o0 + bias_o); o1 = tanhf(o1 + bias_o);
            int bA = 2*p, bB = 2*p + 1;
            float u0 = us[bA*128 + jp], u1 = us[bB*128 + jp];
            float hA = hs1[jp*4 + bA], hB = hs1[jp*4 + bB];
            hs1[jp*4 + bA] = fmaf(u0, o0 - hA, hA);
            hs1[jp*4 + bB] = fmaf(u1, o1 - hB, hB);
        }
        __syncthreads();
    }
    for (int i = tid; i < 512; i += 256)
        g_h1[(b0 + (i & 3)) * 128 + (i >> 2)] = hs1[i];
}

// ============ 4. classifier: out = h1 @ Wfc + bfc ============
__global__ __launch_bounds__(256) void fc_kernel(
    const float* __restrict__ Wfc, const float* __restrict__ bfc, float* __restrict__ out)
{
    __shared__ float h[4 * 128];
    const int tid = threadIdx.x, b0 = blockIdx.x * 4;
    for (int i = tid; i < 512; i += 256) h[i] = g_h1[(b0 + (i >> 7)) * 128 + (i & 127)];
    __syncthreads();
    const int n0 = blockIdx.y * 232;
    const int n1 = (n0 + 232 < NCLS) ? n0 + 232 : NCLS;
    for (int n = n0 + tid; n < n1; n += 256) {
        float a0 = 0.f, a1 = 0.f, a2 = 0.f, a3 = 0.f;
        #pragma unroll 4
        for (int k = 0; k < 128; k++) {
            float w = Wfc[k * NCLS + n];
            a0 = fmaf(h[k], w, a0);       a1 = fmaf(h[128 + k], w, a1);
            a2 = fmaf(h[256 + k], w, a2); a3 = fmaf(h[384 + k], w, a3);
        }
        float bb = bfc[n];
        out[(b0 + 0) * NCLS + n] = a0 + bb;
        out[(b0 + 1) * NCLS + n] = a1 + bb;
        out[(b0 + 2) * NCLS + n] = a2 + bb;
        out[(b0 + 3) * NCLS + n] = a3 + bb;
    }
}

extern "C" void kernel_launch(void* const* d_in, const int* in_sizes, int n_in,
                              void* d_out, int out_size)
{
    const float* X   = (const float*)d_in[0];
    const float* Wr0 = (const float*)d_in[1];  const float* br0 = (const float*)d_in[2];
    const float* Wu0 = (const float*)d_in[3];  const float* bu0 = (const float*)d_in[4];
    const float* Wo0 = (const float*)d_in[5];  const float* bo0 = (const float*)d_in[6];
    const float* Wr1 = (const float*)d_in[7];  const float* br1 = (const float*)d_in[8];
    const float* Wu1 = (const float*)d_in[9];  const float* bu1 = (const float*)d_in[10];
    const float* Wo1 = (const float*)d_in[11]; const float* bo1 = (const float*)d_in[12];
    const float* Wfc = (const float*)d_in[13]; const float* bfc = (const float*)d_in[14];
    float* out = (float*)d_out;

    const int rnn_smem = 12288 * 16;   // 192KB dynamic SMEM for layer-0 weights
    cudaFuncSetAttribute(rnn_kernel, cudaFuncAttributeMaxDynamicSharedMemorySize, rnn_smem);

    pack_kernel<<<(147456 + 255) / 256, 256>>>(Wr0, Wu0, Wo0, Wr1, Wu1, Wo1);
    gemm_x_kernel<<<dim3(6, 5, BATCH), 256>>>(X, Wr0, br0, Wu0, bu0, Wo0, bo0);
    rnn_kernel<<<64, 256, rnn_smem>>>(br1, bu1, bo1);
    fc_kernel<<<dim3(64, 8), 256>>>(Wfc, bfc, out);
}

// round 9
// speedup vs baseline: 1.3219x; 1.0721x over previous
#include <cuda_runtime.h>

#define HID   128
#define INCH  271
#define SEQ   281
#define NCLS  1854
#define BATCH 256

typedef unsigned long long ull;

__device__ __forceinline__ ull pack2(float lo, float hi) {
    ull r; asm("mov.b64 %0, {%1,%2};" : "=l"(r) : "f"(lo), "f"(hi)); return r;
}
__device__ __forceinline__ void unpack2(ull v, float& lo, float& hi) {
    asm("mov.b64 {%0,%1}, %2;" : "=f"(lo), "=f"(hi) : "l"(v));
}
__device__ __forceinline__ ull fma2(ull a, ull b, ull c) {
    ull d; asm("fma.rn.f32x2 %0, %1, %2, %3;" : "=l"(d) : "l"(a), "l"(b), "l"(c)); return d;
}
__device__ __forceinline__ float sigmoidf_(float x) {
    return __fdividef(1.0f, 1.0f + __expf(-x));
}

// -------- device scratch (static, no allocations) --------
__device__ float4 g_G4[(size_t)SEQ * BATCH * 96];   // G[t][b][384] pre-activations
__device__ float4 g_Wq0ru[32 * 256];                // layer0 h-part r|u  (K=128,N=256)
__device__ float4 g_Wq0o [32 * 128];                // layer0 h-part o
__device__ float4 g_Wq1ru[64 * 256];                // layer1 r|u         (K=256,N=256)
__device__ float4 g_Wq1o [64 * 128];                // layer1 o
__device__ float  g_h1[BATCH * HID];                // final h1 [b][k]

// ============ 1. weight repack: [k][j] -> float4{[k4][j][kk]} ============
__global__ void pack_kernel(const float* __restrict__ Wr0, const float* __restrict__ Wu0,
                            const float* __restrict__ Wo0, const float* __restrict__ Wr1,
                            const float* __restrict__ Wu1, const float* __restrict__ Wo1)
{
    int i = blockIdx.x * blockDim.x + threadIdx.x;
    if (i < 32768) {
        int kk = i & 3, j = (i >> 2) & 255, k4 = i >> 10;
        const float* W = (j < 128) ? Wr0 : Wu0;
        ((float*)g_Wq0ru)[i] = W[(271 + k4 * 4 + kk) * 128 + (j & 127)];
    } else if (i < 49152) {
        int v = i - 32768, kk = v & 3, j = (v >> 2) & 127, k4 = v >> 9;
        ((float*)g_Wq0o)[v] = Wo0[(271 + k4 * 4 + kk) * 128 + j];
    } else if (i < 114688) {
        int v = i - 49152, kk = v & 3, j = (v >> 2) & 255, k4 = v >> 10;
        const float* W = (j < 128) ? Wr1 : Wu1;
        ((float*)g_Wq1ru)[v] = W[(k4 * 4 + kk) * 128 + (j & 127)];
    } else if (i < 147456) {
        int v = i - 114688, kk = v & 3, j = (v >> 2) & 127, k4 = v >> 9;
        ((float*)g_Wq1o)[v] = Wo1[(k4 * 4 + kk) * 128 + j];
    }
}

// ============ 2. G[t][b][j] = X[b,:,t] @ W0x[:,j] + bias ============
__global__ __launch_bounds__(256) void gemm_x_kernel(
    const float* __restrict__ X,
    const float* __restrict__ Wr0, const float* __restrict__ br0,
    const float* __restrict__ Wu0, const float* __restrict__ bu0,
    const float* __restrict__ Wo0, const float* __restrict__ bo0)
{
    __shared__ __align__(16) float Xs[16 * 64];
    __shared__ __align__(16) float Ws[16 * 64];
    const int tid = threadIdx.x;
    const int jg0 = blockIdx.x * 64;
    const int t0  = blockIdx.y * 64;
    const int bz  = blockIdx.z;
    const int g   = jg0 >> 7;
    const float* Wsrc = (g == 0) ? Wr0 : (g == 1) ? Wu0 : Wo0;
    const float* bsrc = (g == 0) ? br0 : (g == 1) ? bu0 : bo0;
    const int jj0 = jg0 & 127;
    const int lr = tid >> 6, lc = tid & 63;
    const int ty = tid >> 4, tx = tid & 15;

    ull acc[4][2];
    #pragma unroll
    for (int m = 0; m < 4; m++) { acc[m][0] = 0ull; acc[m][1] = 0ull; }
    const float* Xb = X + (size_t)bz * (INCH * SEQ);

    for (int c0 = 0; c0 < INCH; c0 += 16) {
        #pragma unroll
        for (int i = 0; i < 4; i++) {
            int r = lr + 4 * i, c = c0 + r;
            float xv = 0.f, wv = 0.f;
            if (c < INCH) {
                int tcol = t0 + lc;
                if (tcol < SEQ) xv = Xb[c * SEQ + tcol];
                wv = Wsrc[c * 128 + jj0 + lc];
            }
            Xs[r * 64 + lc] = xv;
            Ws[r * 64 + lc] = wv;
        }
        __syncthreads();
        #pragma unroll
        for (int k = 0; k < 16; k++) {
            float4 a4 = *(const float4*)&Xs[k * 64 + ty * 4];
            ulonglong2 wv = *(const ulonglong2*)&Ws[k * 64 + tx * 4];
            const float* af = (const float*)&a4;
            #pragma unroll
            for (int m = 0; m < 4; m++) {
                ull ap = pack2(af[m], af[m]);
                acc[m][0] = fma2(ap, wv.x, acc[m][0]);
                acc[m][1] = fma2(ap, wv.y, acc[m][1]);
            }
        }
        __syncthreads();
    }
    float b0v = bsrc[jj0 + tx * 4 + 0], b1v = bsrc[jj0 + tx * 4 + 1];
    float b2v = bsrc[jj0 + tx * 4 + 2], b3v = bsrc[jj0 + tx * 4 + 3];
    float* Gf = (float*)g_G4;
    #pragma unroll
    for (int m = 0; m < 4; m++) {
        int tt = t0 + ty * 4 + m;
        if (tt < SEQ) {
            float o0, o1, o2, o3;
            unpack2(acc[m][0], o0, o1); unpack2(acc[m][1], o2, o3);
            *(float4*)&Gf[((size_t)tt * BATCH + bz) * 384 + jg0 + tx * 4] =
                make_float4(o0 + b0v, o1 + b1v, o2 + b2v, o3 + b3v);
        }
    }
}

// ============ 3. recurrence: 128 blocks x 2 batch rows ============
// Layer-0 weights (192KB) resident in dynamic SMEM; layer-1 streamed from L2.
// h-state layout: hs[k*2 + b] so batch-pairs load as 8B words.
__global__ __launch_bounds__(256) void rnn_kernel(
    const float* __restrict__ br1, const float* __restrict__ bu1,
    const float* __restrict__ bo1)
{
    extern __shared__ __align__(16) float4 sW[];   // [0,8192) W0ru, [8192,12288) W0o
    __shared__ __align__(8) float hs0[HID * 2];
    __shared__ __align__(8) float hs1[HID * 2];
    __shared__ __align__(8) float rh [HID * 2];
    __shared__ __align__(8) float us [2 * HID];

    const int tid = threadIdx.x;
    const int b0  = blockIdx.x * 2;
    const int jp  = tid & 127;
    const int p   = tid >> 7;          // batch selector for o-gate stages

    for (int i = tid; i < 12288; i += 256)
        sW[i] = (i < 8192) ? g_Wq0ru[i] : g_Wq0o[i - 8192];
    for (int i = tid; i < HID * 2; i += 256) { hs0[i] = 0.f; hs1[i] = 0.f; }
    __syncthreads();

    const float bias_ru = (tid < 128) ? br1[tid] : bu1[tid - 128];
    const float bias_o  = bo1[jp];
    const float* Gf = (const float*)g_G4;
    const float4* sW0o = sW + 8192;

    // prefetch G for t=0
    const float* Gt0 = Gf + (size_t)b0 * 384;
    float gx0 = Gt0[tid];
    float gx1 = Gt0[384 + tid];
    float go  = Gt0[(size_t)p * 384 + 256 + jp];

    for (int t = 0; t < SEQ; t++) {
        // ---- layer0 r,u (SMEM weights): thread = col j, batch pair ----
        ull a = 0ull;
        #pragma unroll 8
        for (int k4 = 0; k4 < 32; k4++) {
            float4 w = sW[k4 * 256 + tid];
            const float* wf = (const float*)&w;
            #pragma unroll
            for (int kk = 0; kk < 4; kk++) {
                ull hv = *(const ull*)&hs0[(k4 * 4 + kk) * 2];
                a = fma2(hv, pack2(wf[kk], wf[kk]), a);
            }
        }
        {
            float v0, v1; unpack2(a, v0, v1);
            v0 = sigmoidf_(v0 + gx0); v1 = sigmoidf_(v1 + gx1);
            if (tid < 128) {
                float2 h = *(const float2*)&hs0[tid * 2];
                *(float2*)&rh[tid * 2] = make_float2(v0 * h.x, v1 * h.y);
            } else {
                int jj = tid - 128;
                us[jj] = v0; us[128 + jj] = v1;
            }
        }
        __syncthreads();

        // ---- layer0 o + h0 update (SMEM weights): thread = (jp, batch p) ----
        float acc = 0.f;
        #pragma unroll 8
        for (int k4 = 0; k4 < 32; k4++) {
            float4 w = sW0o[k4 * 128 + jp];
            const float* wf = (const float*)&w;
            #pragma unroll
            for (int kk = 0; kk < 4; kk++)
                acc = fmaf(rh[(k4 * 4 + kk) * 2 + p], wf[kk], acc);
        }
        {
            float o = tanhf(acc + go);
            float u = us[p * 128 + jp];
            float h = hs0[jp * 2 + p];
            hs0[jp * 2 + p] = fmaf(u, o - h, h);
        }
        __syncthreads();

        // prefetch G for t+1 (hidden behind stages 3-4)
        float ngx0 = 0.f, ngx1 = 0.f, ngo = 0.f;
        if (t + 1 < SEQ) {
            const float* Gn = Gf + ((size_t)(t + 1) * BATCH + b0) * 384;
            ngx0 = Gn[tid]; ngx1 = Gn[384 + tid]; ngo = Gn[(size_t)p * 384 + 256 + jp];
        }

        // ---- layer1 r,u (L2 weights): K=256 = [h0_new | h1] ----
        a = 0ull;
        #pragma unroll 8
        for (int k4 = 0; k4 < 32; k4++) {
            float4 w = g_Wq1ru[k4 * 256 + tid];
            const float* wf = (const float*)&w;
            #pragma unroll
            for (int kk = 0; kk < 4; kk++) {
                ull hv = *(const ull*)&hs0[(k4 * 4 + kk) * 2];
                a = fma2(hv, pack2(wf[kk], wf[kk]), a);
            }
        }
        #pragma unroll 8
        for (int k4 = 0; k4 < 32; k4++) {
            float4 w = g_Wq1ru[(k4 + 32) * 256 + tid];
            const float* wf = (const float*)&w;
            #pragma unroll
            for (int kk = 0; kk < 4; kk++) {
                ull hv = *(const ull*)&hs1[(k4 * 4 + kk) * 2];
                a = fma2(hv, pack2(wf[kk], wf[kk]), a);
            }
        }
        {
            float v0, v1; unpack2(a, v0, v1);
            v0 = sigmoidf_(v0 + bias_ru); v1 = sigmoidf_(v1 + bias_ru);
            if (tid < 128) {
                float2 h = *(const float2*)&hs1[tid * 2];
                *(float2*)&rh[tid * 2] = make_float2(v0 * h.x, v1 * h.y);
            } else {
                int jj = tid - 128;
                us[jj] = v0; us[128 + jj] = v1;
            }
        }
        __syncthreads();

        // ---- layer1 o + h1 update (L2 weights): K=256 = [h0_new | r1*h1] ----
        acc = 0.f;
        #pragma unroll 8
        for (int k4 = 0; k4 < 32; k4++) {
            float4 w = g_Wq1o[k4 * 128 + jp];
            const float* wf = (const float*)&w;
            #pragma unroll
            for (int kk = 0; kk < 4; kk++)
                acc = fmaf(hs0[(k4 * 4 + kk) * 2 + p], wf[kk], acc);
        }
        #pragma unroll 8
        for (int k4 = 0; k4 < 32; k4++) {
            float4 w = g_Wq1o[(k4 + 32) * 128 + jp];
            const float* wf = (const float*)&w;
            #pragma unroll
            for (int kk = 0; kk < 4; kk++)
                acc = fmaf(rh[(k4 * 4 + kk) * 2 + p], wf[kk], acc);
        }
        {
            float o = tanhf(acc + bias_o);
            float u = us[p * 128 + jp];
            float h = hs1[jp * 2 + p];
            hs1[jp * 2 + p] = fmaf(u, o - h, h);
        }
        __syncthreads();

        gx0 = ngx0; gx1 = ngx1; go = ngo;
    }
    for (int i = tid; i < HID * 2; i += 256)
        g_h1[(b0 + (i & 1)) * 128 + (i >> 1)] = hs1[i];
}

// ============ 4. classifier: out = h1 @ Wfc + bfc ============
__global__ __launch_bounds__(256) void fc_kernel(
    const float* __restrict__ Wfc, const float* __restrict__ bfc, float* __restrict__ out)
{
    __shared__ float h[4 * 128];
    const int tid = threadIdx.x, b0 = blockIdx.x * 4;
    for (int i = tid; i < 512; i += 256) h[i] = g_h1[(b0 + (i >> 7)) * 128 + (i & 127)];
    __syncthreads();
    const int n0 = blockIdx.y * 232;
    const int n1 = (n0 + 232 < NCLS) ? n0 + 232 : NCLS;
    for (int n = n0 + tid; n < n1; n += 256) {
        float a0 = 0.f, a1 = 0.f, a2 = 0.f, a3 = 0.f;
        #pragma unroll 4
        for (int k = 0; k < 128; k++) {
            float w = Wfc[k * NCLS + n];
            a0 = fmaf(h[k], w, a0);       a1 = fmaf(h[128 + k], w, a1);
            a2 = fmaf(h[256 + k], w, a2); a3 = fmaf(h[384 + k], w, a3);
        }
        float bb = bfc[n];
        out[(b0 + 0) * NCLS + n] = a0 + bb;
        out[(b0 + 1) * NCLS + n] = a1 + bb;
        out[(b0 + 2) * NCLS + n] = a2 + bb;
        out[(b0 + 3) * NCLS + n] = a3 + bb;
    }
}

extern "C" void kernel_launch(void* const* d_in, const int* in_sizes, int n_in,
                              void* d_out, int out_size)
{
    const float* X   = (const float*)d_in[0];
    const float* Wr0 = (const float*)d_in[1];  const float* br0 = (const float*)d_in[2];
    const float* Wu0 = (const float*)d_in[3];  const float* bu0 = (const float*)d_in[4];
    const float* Wo0 = (const float*)d_in[5];  const float* bo0 = (const float*)d_in[6];
    const float* Wr1 = (const float*)d_in[7];  const float* br1 = (const float*)d_in[8];
    const float* Wu1 = (const float*)d_in[9];  const float* bu1 = (const float*)d_in[10];
    const float* Wo1 = (const float*)d_in[11]; const float* bo1 = (const float*)d_in[12];
    const float* Wfc = (const float*)d_in[13]; const float* bfc = (const float*)d_in[14];
    float* out = (float*)d_out;

    const int rnn_smem = 12288 * 16;   // 192KB dynamic SMEM for layer-0 weights
    cudaFuncSetAttribute(rnn_kernel, cudaFuncAttributeMaxDynamicSharedMemorySize, rnn_smem);

    pack_kernel<<<(147456 + 255) / 256, 256>>>(Wr0, Wu0, Wo0, Wr1, Wu1, Wo1);
    gemm_x_kernel<<<dim3(6, 5, BATCH), 256>>>(X, Wr0, br0, Wu0, bu0, Wo0, bo0);
    rnn_kernel<<<128, 256, rnn_smem>>>(br1, bu1, bo1);
    fc_kernel<<<dim3(64, 8), 256>>>(Wfc, bfc, out);
}

// round 11
// speedup vs baseline: 1.3849x; 1.0477x over previous
#include <cuda_runtime.h>
#include <cuda_fp16.h>

#define HID   128
#define INCH  271
#define SEQ   281
#define NCLS  1854
#define BATCH 256

typedef unsigned long long ull;

__device__ __forceinline__ ull pack2(float lo, float hi) {
    ull r; asm("mov.b64 %0, {%1,%2};" : "=l"(r) : "f"(lo), "f"(hi)); return r;
}
__device__ __forceinline__ void unpack2(ull v, float& lo, float& hi) {
    asm("mov.b64 {%0,%1}, %2;" : "=f"(lo), "=f"(hi) : "l"(v));
}
__device__ __forceinline__ ull fma2(ull a, ull b, ull c) {
    ull d; asm("fma.rn.f32x2 %0, %1, %2, %3;" : "=l"(d) : "l"(a), "l"(b), "l"(c)); return d;
}
__device__ __forceinline__ float sigmoidf_(float x) {
    return __fdividef(1.0f, 1.0f + __expf(-x));
}
// split an 8-byte word of 4 halves into 4 floats
__device__ __forceinline__ void h4_to_f4(ull w, float& f0, float& f1, float& f2, float& f3) {
    __half2 h01 = *reinterpret_cast<__half2*>(&w);
    __half2 h23 = *(reinterpret_cast<__half2*>(&w) + 1);
    float2 a = __half22float2(h01), b = __half22float2(h23);
    f0 = a.x; f1 = a.y; f2 = b.x; f3 = b.y;
}

// -------- device scratch (static, no allocations) --------
__device__ float4 g_G4[(size_t)SEQ * BATCH * 96];   // G[t][b][384] pre-activations (fp32)
// fp16 packed recurrent weights: entry = 4 halves (one k4-group for one column)
__device__ ull g_Hq0ru[32 * 256];                   // layer0 h-part r|u  (K=128,N=256)
__device__ ull g_Hq0o [32 * 128];                   // layer0 h-part o   (L2-streamed)
__device__ ull g_Hq1ru[64 * 256];                   // layer1 r|u         (K=256,N=256)
__device__ ull g_Hq1o [64 * 128];                   // layer1 o          (L2-streamed)
__device__ float g_h1[BATCH * HID];                 // final h1 [b][k]

// ============ 1. weight repack: fp32 [k][j] -> fp16 {[k4][j][kk]} ============
__global__ void pack_kernel(const float* __restrict__ Wr0, const float* __restrict__ Wu0,
                            const float* __restrict__ Wo0, const float* __restrict__ Wr1,
                            const float* __restrict__ Wu1, const float* __restrict__ Wo1)
{
    int i = blockIdx.x * blockDim.x + threadIdx.x;
    if (i < 32768) {
        int kk = i & 3, j = (i >> 2) & 255, k4 = i >> 10;
        const float* W = (j < 128) ? Wr0 : Wu0;
        ((__half*)g_Hq0ru)[i] = __float2half_rn(W[(271 + k4 * 4 + kk) * 128 + (j & 127)]);
    } else if (i < 49152) {
        int v = i - 32768, kk = v & 3, j = (v >> 2) & 127, k4 = v >> 9;
        ((__half*)g_Hq0o)[v] = __float2half_rn(Wo0[(271 + k4 * 4 + kk) * 128 + j]);
    } else if (i < 114688) {
        int v = i - 49152, kk = v & 3, j = (v >> 2) & 255, k4 = v >> 10;
        const float* W = (j < 128) ? Wr1 : Wu1;
        ((__half*)g_Hq1ru)[v] = __float2half_rn(W[(k4 * 4 + kk) * 128 + (j & 127)]);
    } else if (i < 147456) {
        int v = i - 114688, kk = v & 3, j = (v >> 2) & 127, k4 = v >> 9;
        ((__half*)g_Hq1o)[v] = __float2half_rn(Wo1[(k4 * 4 + kk) * 128 + j]);
    }
}

// ============ 2. G[t][b][j] = X[b,:,t] @ W0x[:,j] + bias (fp32) ============
__global__ __launch_bounds__(256) void gemm_x_kernel(
    const float* __restrict__ X,
    const float* __restrict__ Wr0, const float* __restrict__ br0,
    const float* __restrict__ Wu0, const float* __restrict__ bu0,
    const float* __restrict__ Wo0, const float* __restrict__ bo0)
{
    __shared__ __align__(16) float Xs[16 * 64];
    __shared__ __align__(16) float Ws[16 * 64];
    const int tid = threadIdx.x;
    const int jg0 = blockIdx.x * 64;
    const int t0  = blockIdx.y * 64;
    const int bz  = blockIdx.z;
    const int g   = jg0 >> 7;
    const float* Wsrc = (g == 0) ? Wr0 : (g == 1) ? Wu0 : Wo0;
    const float* bsrc = (g == 0) ? br0 : (g == 1) ? bu0 : bo0;
    const int jj0 = jg0 & 127;
    const int lr = tid >> 6, lc = tid & 63;
    const int ty = tid >> 4, tx = tid & 15;

    ull acc[4][2];
    #pragma unroll
    for (int m = 0; m < 4; m++) { acc[m][0] = 0ull; acc[m][1] = 0ull; }
    const float* Xb = X + (size_t)bz * (INCH * SEQ);

    for (int c0 = 0; c0 < INCH; c0 += 16) {
        #pragma unroll
        for (int i = 0; i < 4; i++) {
            int r = lr + 4 * i, c = c0 + r;
            float xv = 0.f, wv = 0.f;
            if (c < INCH) {
                int tcol = t0 + lc;
                if (tcol < SEQ) xv = Xb[c * SEQ + tcol];
                wv = Wsrc[c * 128 + jj0 + lc];
            }
            Xs[r * 64 + lc] = xv;
            Ws[r * 64 + lc] = wv;
        }
        __syncthreads();
        #pragma unroll
        for (int k = 0; k < 16; k++) {
            float4 a4 = *(const float4*)&Xs[k * 64 + ty * 4];
            ulonglong2 wv = *(const ulonglong2*)&Ws[k * 64 + tx * 4];
            const float* af = (const float*)&a4;
            #pragma unroll
            for (int m = 0; m < 4; m++) {
                ull ap = pack2(af[m], af[m]);
                acc[m][0] = fma2(ap, wv.x, acc[m][0]);
                acc[m][1] = fma2(ap, wv.y, acc[m][1]);
            }
        }
        __syncthreads();
    }
    float b0v = bsrc[jj0 + tx * 4 + 0], b1v = bsrc[jj0 + tx * 4 + 1];
    float b2v = bsrc[jj0 + tx * 4 + 2], b3v = bsrc[jj0 + tx * 4 + 3];
    float* Gf = (float*)g_G4;
    #pragma unroll
    for (int m = 0; m < 4; m++) {
        int tt = t0 + ty * 4 + m;
        if (tt < SEQ) {
            float o0, o1, o2, o3;
            unpack2(acc[m][0], o0, o1); unpack2(acc[m][1], o2, o3);
            *(float4*)&Gf[((size_t)tt * BATCH + bz) * 384 + jg0 + tx * 4] =
                make_float4(o0 + b0v, o1 + b1v, o2 + b2v, o3 + b3v);
        }
    }
}

// ============ 3. recurrence: 128 blocks x 2 batch rows ============
// fp16 weights: W0ru + W1ru resident in 192KB dynamic SMEM (within the 227KB
// opt-in limit incl. 4KB static shared); W0o + W1o streamed from L2.
__global__ __launch_bounds__(256) void rnn_kernel(
    const float* __restrict__ br1, const float* __restrict__ bu1,
    const float* __restrict__ bo1)
{
    extern __shared__ __align__(16) ull sW[];   // [0,8192) W0ru | [8192,24576) W1ru
    __shared__ __align__(8) float hs0[HID * 2];
    __shared__ __align__(8) float hs1[HID * 2];
    __shared__ __align__(8) float rh [HID * 2];
    __shared__ __align__(8) float us [2 * HID];

    const int tid = threadIdx.x;
    const int b0  = blockIdx.x * 2;
    const int jp  = tid & 127;
    const int p   = tid >> 7;          // batch selector for o-gate stages

    for (int i = tid; i < 24576; i += 256)
        sW[i] = (i < 8192) ? g_Hq0ru[i] : g_Hq1ru[i - 8192];
    for (int i = tid; i < HID * 2; i += 256) { hs0[i] = 0.f; hs1[i] = 0.f; }
    __syncthreads();

    const float bias_ru = (tid < 128) ? br1[tid] : bu1[tid - 128];
    const float bias_o  = bo1[jp];
    const float* Gf = (const float*)g_G4;
    const ull* sW1ru = sW + 8192;

    // prefetch G for t=0
    const float* Gt0 = Gf + (size_t)b0 * 384;
    float gx0 = Gt0[tid];
    float gx1 = Gt0[384 + tid];
    float go  = Gt0[(size_t)p * 384 + 256 + jp];

    for (int t = 0; t < SEQ; t++) {
        // ---- layer0 r,u (SMEM fp16): thread = col j, batch pair ----
        ull a = 0ull;
        #pragma unroll 8
        for (int k4 = 0; k4 < 32; k4++) {
            float f0, f1, f2, f3;
            h4_to_f4(sW[k4 * 256 + tid], f0, f1, f2, f3);
            const ull* hv = (const ull*)&hs0[k4 * 8];
            a = fma2(hv[0], pack2(f0, f0), a);
            a = fma2(hv[1], pack2(f1, f1), a);
            a = fma2(hv[2], pack2(f2, f2), a);
            a = fma2(hv[3], pack2(f3, f3), a);
        }
        {
            float v0, v1; unpack2(a, v0, v1);
            v0 = sigmoidf_(v0 + gx0); v1 = sigmoidf_(v1 + gx1);
            if (tid < 128) {
                float2 h = *(const float2*)&hs0[tid * 2];
                *(float2*)&rh[tid * 2] = make_float2(v0 * h.x, v1 * h.y);
            } else {
                int jj = tid - 128;
                us[jj] = v0; us[128 + jj] = v1;
            }
        }
        __syncthreads();

        // ---- layer0 o + h0 update (W0o fp16 from L2): thread = (jp, batch p) ----
        float acc = 0.f;
        #pragma unroll 8
        for (int k4 = 0; k4 < 32; k4++) {
            float f0, f1, f2, f3;
            h4_to_f4(g_Hq0o[k4 * 128 + jp], f0, f1, f2, f3);
            const float* hv = &rh[k4 * 8 + p];
            acc = fmaf(hv[0], f0, acc);
            acc = fmaf(hv[2], f1, acc);
            acc = fmaf(hv[4], f2, acc);
            acc = fmaf(hv[6], f3, acc);
        }
        {
            float o = tanhf(acc + go);
            float u = us[p * 128 + jp];
            float h = hs0[jp * 2 + p];
            hs0[jp * 2 + p] = fmaf(u, o - h, h);
        }
        __syncthreads();

        // prefetch G for t+1 (hidden behind stages 3-4)
        float ngx0 = 0.f, ngx1 = 0.f, ngo = 0.f;
        if (t + 1 < SEQ) {
            const float* Gn = Gf + ((size_t)(t + 1) * BATCH + b0) * 384;
            ngx0 = Gn[tid]; ngx1 = Gn[384 + tid]; ngo = Gn[(size_t)p * 384 + 256 + jp];
        }

        // ---- layer1 r,u (SMEM fp16): K=256 = [h0_new | h1] ----
        a = 0ull;
        #pragma unroll 8
        for (int k4 = 0; k4 < 32; k4++) {
            float f0, f1, f2, f3;
            h4_to_f4(sW1ru[k4 * 256 + tid], f0, f1, f2, f3);
            const ull* hv = (const ull*)&hs0[k4 * 8];
            a = fma2(hv[0], pack2(f0, f0), a);
            a = fma2(hv[1], pack2(f1, f1), a);
            a = fma2(hv[2], pack2(f2, f2), a);
            a = fma2(hv[3], pack2(f3, f3), a);
        }
        #pragma unroll 8
        for (int k4 = 0; k4 < 32; k4++) {
            float f0, f1, f2, f3;
            h4_to_f4(sW1ru[(k4 + 32) * 256 + tid], f0, f1, f2, f3);
            const ull* hv = (const ull*)&hs1[k4 * 8];
            a = fma2(hv[0], pack2(f0, f0), a);
            a = fma2(hv[1], pack2(f1, f1), a);
            a = fma2(hv[2], pack2(f2, f2), a);
            a = fma2(hv[3], pack2(f3, f3), a);
        }
        {
            float v0, v1; unpack2(a, v0, v1);
            v0 = sigmoidf_(v0 + bias_ru); v1 = sigmoidf_(v1 + bias_ru);
            if (tid < 128) {
                float2 h = *(const float2*)&hs1[tid * 2];
                *(float2*)&rh[tid * 2] = make_float2(v0 * h.x, v1 * h.y);
            } else {
                int jj = tid - 128;
                us[jj] = v0; us[128 + jj] = v1;
            }
        }
        __syncthreads();

        // ---- layer1 o + h1 update (W1o fp16 from L2): K=256 = [h0_new | r1*h1] ----
        acc = 0.f;
        #pragma unroll 8
        for (int k4 = 0; k4 < 32; k4++) {
            float f0, f1, f2, f3;
            h4_to_f4(g_Hq1o[k4 * 128 + jp], f0, f1, f2, f3);
            const float* hv = &hs0[k4 * 8 + p];
            acc = fmaf(hv[0], f0, acc);
            acc = fmaf(hv[2], f1, acc);
            acc = fmaf(hv[4], f2, acc);
            acc = fmaf(hv[6], f3, acc);
        }
        #pragma unroll 8
        for (int k4 = 0; k4 < 32; k4++) {
            float f0, f1, f2, f3;
            h4_to_f4(g_Hq1o[(k4 + 32) * 128 + jp], f0, f1, f2, f3);
            const float* hv = &rh[k4 * 8 + p];
            acc = fmaf(hv[0], f0, acc);
            acc = fmaf(hv[2], f1, acc);
            acc = fmaf(hv[4], f2, acc);
            acc = fmaf(hv[6], f3, acc);
        }
        {
            float o = tanhf(acc + bias_o);
            float u = us[p * 128 + jp];
            float h = hs1[jp * 2 + p];
            hs1[jp * 2 + p] = fmaf(u, o - h, h);
        }
        __syncthreads();

        gx0 = ngx0; gx1 = ngx1; go = ngo;
    }
    for (int i = tid; i < HID * 2; i += 256)
        g_h1[(b0 + (i & 1)) * 128 + (i >> 1)] = hs1[i];
}

// ============ 4. classifier: out = h1 @ Wfc + bfc ============
__global__ __launch_bounds__(256) void fc_kernel(
    const float* __restrict__ Wfc, const float* __restrict__ bfc, float* __restrict__ out)
{
    __shared__ float h[4 * 128];
    const int tid = threadIdx.x, b0 = blockIdx.x * 4;
    for (int i = tid; i < 512; i += 256) h[i] = g_h1[(b0 + (i >> 7)) * 128 + (i & 127)];
    __syncthreads();
    const int n0 = blockIdx.y * 232;
    const int n1 = (n0 + 232 < NCLS) ? n0 + 232 : NCLS;
    for (int n = n0 + tid; n < n1; n += 256) {
        float a0 = 0.f, a1 = 0.f, a2 = 0.f, a3 = 0.f;
        #pragma unroll 4
        for (int k = 0; k < 128; k++) {
            float w = Wfc[k * NCLS + n];
            a0 = fmaf(h[k], w, a0);       a1 = fmaf(h[128 + k], w, a1);
            a2 = fmaf(h[256 + k], w, a2); a3 = fmaf(h[384 + k], w, a3);
        }
        float bb = bfc[n];
        out[(b0 + 0) * NCLS + n] = a0 + bb;
        out[(b0 + 1) * NCLS + n] = a1 + bb;
        out[(b0 + 2) * NCLS + n] = a2 + bb;
        out[(b0 + 3) * NCLS + n] = a3 + bb;
    }
}

extern "C" void kernel_launch(void* const* d_in, const int* in_sizes, int n_in,
                              void* d_out, int out_size)
{
    const float* X   = (const float*)d_in[0];
    const float* Wr0 = (const float*)d_in[1];  const float* br0 = (const float*)d_in[2];
    const float* Wu0 = (const float*)d_in[3];  const float* bu0 = (const float*)d_in[4];
    const float* Wo0 = (const float*)d_in[5];  const float* bo0 = (const float*)d_in[6];
    const float* Wr1 = (const float*)d_in[7];  const float* br1 = (const float*)d_in[8];
    const float* Wu1 = (const float*)d_in[9];  const float* bu1 = (const float*)d_in[10];
    const float* Wo1 = (const float*)d_in[11]; const float* bo1 = (const float*)d_in[12];
    const float* Wfc = (const float*)d_in[13]; const float* bfc = (const float*)d_in[14];
    float* out = (float*)d_out;

    const int rnn_smem = 24576 * 8;   // 192KB dynamic SMEM: fp16 W0ru | W1ru
    cudaFuncSetAttribute(rnn_kernel, cudaFuncAttributeMaxDynamicSharedMemorySize, rnn_smem);

    pack_kernel<<<(147456 + 255) / 256, 256>>>(Wr0, Wu0, Wo0, Wr1, Wu1, Wo1);
    gemm_x_kernel<<<dim3(6, 5, BATCH), 256>>>(X, Wr0, br0, Wu0, bu0, Wo0, bo0);
    rnn_kernel<<<128, 256, rnn_smem>>>(br1, bu1, bo1);
    fc_kernel<<<dim3(64, 8), 256>>>(Wfc, bfc, out);
}

// round 12
// speedup vs baseline: 2.3820x; 1.7200x over previous
#include <cuda_runtime.h>
#include <cuda_fp16.h>

#define HID   128
#define INCH  271
#define SEQ   281
#define NCLS  1854
#define BATCH 256

typedef unsigned long long ull;

__device__ __forceinline__ ull pack2(float lo, float hi) {
    ull r; asm("mov.b64 %0, {%1,%2};" : "=l"(r) : "f"(lo), "f"(hi)); return r;
}
__device__ __forceinline__ void unpack2(ull v, float& lo, float& hi) {
    asm("mov.b64 {%0,%1}, %2;" : "=f"(lo), "=f"(hi) : "l"(v));
}
__device__ __forceinline__ ull fma2(ull a, ull b, ull c) {
    ull d; asm("fma.rn.f32x2 %0, %1, %2, %3;" : "=l"(d) : "l"(a), "l"(b), "l"(c)); return d;
}
__device__ __forceinline__ float sigmoidf_(float x) {
    return __fdividef(1.0f, 1.0f + __expf(-x));
}
// split an 8-byte word of 4 halves into 4 floats
__device__ __forceinline__ void h4_to_f4(ull w, float& f0, float& f1, float& f2, float& f3) {
    __half2 h01 = *reinterpret_cast<__half2*>(&w);
    __half2 h23 = *(reinterpret_cast<__half2*>(&w) + 1);
    float2 a = __half22float2(h01), b = __half22float2(h23);
    f0 = a.x; f1 = a.y; f2 = b.x; f3 = b.y;
}

// -------- device scratch (static, no allocations) --------
__device__ float4 g_G4[(size_t)SEQ * BATCH * 96];   // G[t][b][384] pre-activations (fp32)
__device__ ull g_Hq0ru[32 * 256];                   // layer0 h-part r|u  (K=128,N=256)
__device__ ull g_Hq0o [32 * 128];                   // layer0 h-part o   (L2-streamed)
__device__ ull g_Hq1ru[64 * 256];                   // layer1 r|u         (K=256,N=256)
__device__ ull g_Hq1o [64 * 128];                   // layer1 o          (L2-streamed)
__device__ float g_h1[BATCH * HID];                 // final h1 [b][k]

// ============ 1. weight repack: fp32 [k][j] -> fp16 {[k4][j][kk]} ============
__global__ void pack_kernel(const float* __restrict__ Wr0, const float* __restrict__ Wu0,
                            const float* __restrict__ Wo0, const float* __restrict__ Wr1,
                            const float* __restrict__ Wu1, const float* __restrict__ Wo1)
{
    int i = blockIdx.x * blockDim.x + threadIdx.x;
    if (i < 32768) {
        int kk = i & 3, j = (i >> 2) & 255, k4 = i >> 10;
        const float* W = (j < 128) ? Wr0 : Wu0;
        ((__half*)g_Hq0ru)[i] = __float2half_rn(W[(271 + k4 * 4 + kk) * 128 + (j & 127)]);
    } else if (i < 49152) {
        int v = i - 32768, kk = v & 3, j = (v >> 2) & 127, k4 = v >> 9;
        ((__half*)g_Hq0o)[v] = __float2half_rn(Wo0[(271 + k4 * 4 + kk) * 128 + j]);
    } else if (i < 114688) {
        int v = i - 49152, kk = v & 3, j = (v >> 2) & 255, k4 = v >> 10;
        const float* W = (j < 128) ? Wr1 : Wu1;
        ((__half*)g_Hq1ru)[v] = __float2half_rn(W[(k4 * 4 + kk) * 128 + (j & 127)]);
    } else if (i < 147456) {
        int v = i - 114688, kk = v & 3, j = (v >> 2) & 127, k4 = v >> 9;
        ((__half*)g_Hq1o)[v] = __float2half_rn(Wo1[(k4 * 4 + kk) * 128 + j]);
    }
}

// ============ 2. G[t][b][j] = X[b,:,t] @ W0x[:,j] + bias (fp32) ============
__global__ __launch_bounds__(256) void gemm_x_kernel(
    const float* __restrict__ X,
    const float* __restrict__ Wr0, const float* __restrict__ br0,
    const float* __restrict__ Wu0, const float* __restrict__ bu0,
    const float* __restrict__ Wo0, const float* __restrict__ bo0)
{
    __shared__ __align__(16) float Xs[16 * 64];
    __shared__ __align__(16) float Ws[16 * 64];
    const int tid = threadIdx.x;
    const int jg0 = blockIdx.x * 64;
    const int t0  = blockIdx.y * 64;
    const int bz  = blockIdx.z;
    const int g   = jg0 >> 7;
    const float* Wsrc = (g == 0) ? Wr0 : (g == 1) ? Wu0 : Wo0;
    const float* bsrc = (g == 0) ? br0 : (g == 1) ? bu0 : bo0;
    const int jj0 = jg0 & 127;
    const int lr = tid >> 6, lc = tid & 63;
    const int ty = tid >> 4, tx = tid & 15;

    ull acc[4][2];
    #pragma unroll
    for (int m = 0; m < 4; m++) { acc[m][0] = 0ull; acc[m][1] = 0ull; }
    const float* Xb = X + (size_t)bz * (INCH * SEQ);

    for (int c0 = 0; c0 < INCH; c0 += 16) {
        #pragma unroll
        for (int i = 0; i < 4; i++) {
            int r = lr + 4 * i, c = c0 + r;
            float xv = 0.f, wv = 0.f;
            if (c < INCH) {
                int tcol = t0 + lc;
                if (tcol < SEQ) xv = Xb[c * SEQ + tcol];
                wv = Wsrc[c * 128 + jj0 + lc];
            }
            Xs[r * 64 + lc] = xv;
            Ws[r * 64 + lc] = wv;
        }
        __syncthreads();
        #pragma unroll
        for (int k = 0; k < 16; k++) {
            float4 a4 = *(const float4*)&Xs[k * 64 + ty * 4];
            ulonglong2 wv = *(const ulonglong2*)&Ws[k * 64 + tx * 4];
            const float* af = (const float*)&a4;
            #pragma unroll
            for (int m = 0; m < 4; m++) {
                ull ap = pack2(af[m], af[m]);
                acc[m][0] = fma2(ap, wv.x, acc[m][0]);
                acc[m][1] = fma2(ap, wv.y, acc[m][1]);
            }
        }
        __syncthreads();
    }
    float b0v = bsrc[jj0 + tx * 4 + 0], b1v = bsrc[jj0 + tx * 4 + 1];
    float b2v = bsrc[jj0 + tx * 4 + 2], b3v = bsrc[jj0 + tx * 4 + 3];
    float* Gf = (float*)g_G4;
    #pragma unroll
    for (int m = 0; m < 4; m++) {
        int tt = t0 + ty * 4 + m;
        if (tt < SEQ) {
            float o0, o1, o2, o3;
            unpack2(acc[m][0], o0, o1); unpack2(acc[m][1], o2, o3);
            *(float4*)&Gf[((size_t)tt * BATCH + bz) * 384 + jg0 + tx * 4] =
                make_float4(o0 + b0v, o1 + b1v, o2 + b2v, o3 + b3v);
        }
    }
}

// ============ 3. recurrence: 128 blocks x 2 batch rows, 512 threads ============
// K-split: kh = tid>>8 takes half the k-range of every stage; halves reduce
// through SMEM. 16 warps/block = 4/SMSP for latency hiding.
// fp16 weights: W0ru + W1ru resident in 192KB dynamic SMEM; W0o/W1o from L2.
__global__ __launch_bounds__(512) void rnn_kernel(
    const float* __restrict__ br1, const float* __restrict__ bu1,
    const float* __restrict__ bo1)
{
    extern __shared__ __align__(16) ull sW[];   // [0,8192) W0ru | [8192,24576) W1ru
    __shared__ __align__(8) float hs0[HID * 2];
    __shared__ __align__(8) float hs1[HID * 2];
    __shared__ __align__(8) float rh [HID * 2];
    __shared__ __align__(8) float us [2 * HID];
    __shared__ __align__(16) ull   red1[256];   // stage-1/3 partials (packed b-pair)
    __shared__ __align__(8)  float red2[256];   // stage-2/4 partials

    const int tid = threadIdx.x;
    const int b0  = blockIdx.x * 2;
    const int j   = tid & 255;         // output column for ru stages
    const int kh  = tid >> 8;          // k-half selector (uniform per warp)
    const int jp  = tid & 127;
    const int p   = (tid >> 7) & 1;    // batch selector for o-gate stages

    for (int i = tid; i < 24576; i += 512)
        sW[i] = (i < 8192) ? g_Hq0ru[i] : g_Hq1ru[i - 8192];
    for (int i = tid; i < HID * 2; i += 512) { hs0[i] = 0.f; hs1[i] = 0.f; }
    __syncthreads();

    const float bias_ru = (j < 128) ? br1[j] : bu1[j - 128];
    const float bias_o  = bo1[jp];
    const float* Gf = (const float*)g_G4;
    const ull* sW1ru = sW + 8192;

    // G prefetch (only kh==0 threads consume gx/go)
    const float* Gt0 = Gf + (size_t)b0 * 384;
    float gx0 = Gt0[j];
    float gx1 = Gt0[384 + j];
    float go  = Gt0[(size_t)p * 384 + 256 + jp];

    for (int t = 0; t < SEQ; t++) {
        // ---- stage 1: layer0 r,u. thread=(j, kh), 16 k4 each ----
        ull a = 0ull;
        #pragma unroll
        for (int k4o = 0; k4o < 16; k4o++) {
            int k4 = kh * 16 + k4o;
            float f0, f1, f2, f3;
            h4_to_f4(sW[k4 * 256 + j], f0, f1, f2, f3);
            ulonglong2 h01 = *(const ulonglong2*)&hs0[k4 * 8];
            ulonglong2 h23 = *(const ulonglong2*)&hs0[k4 * 8 + 4];
            a = fma2(h01.x, pack2(f0, f0), a);
            a = fma2(h01.y, pack2(f1, f1), a);
            a = fma2(h23.x, pack2(f2, f2), a);
            a = fma2(h23.y, pack2(f3, f3), a);
        }
        if (kh) red1[j] = a;
        __syncthreads();
        if (!kh) {
            float v0, v1, w0, w1;
            unpack2(a, v0, v1); unpack2(red1[j], w0, w1);
            v0 = sigmoidf_(v0 + w0 + gx0); v1 = sigmoidf_(v1 + w1 + gx1);
            if (j < 128) {
                float2 h = *(const float2*)&hs0[j * 2];
                *(float2*)&rh[j * 2] = make_float2(v0 * h.x, v1 * h.y);
            } else {
                int jj = j - 128;
                us[jj] = v0; us[128 + jj] = v1;
            }
        }
        __syncthreads();

        // ---- stage 2: layer0 o + h0 update. thread=(jp, p, kh), 16 k4 each ----
        float acc = 0.f;
        #pragma unroll
        for (int k4o = 0; k4o < 16; k4o++) {
            int k4 = kh * 16 + k4o;
            float f0, f1, f2, f3;
            h4_to_f4(g_Hq0o[k4 * 128 + jp], f0, f1, f2, f3);
            const float* hv = &rh[k4 * 8 + p];
            acc = fmaf(hv[0], f0, acc);
            acc = fmaf(hv[2], f1, acc);
            acc = fmaf(hv[4], f2, acc);
            acc = fmaf(hv[6], f3, acc);
        }
        if (kh) red2[p * 128 + jp] = acc;
        __syncthreads();
        if (!kh) {
            float o = tanhf(acc + red2[p * 128 + jp] + go);
            float u = us[p * 128 + jp];
            float h = hs0[jp * 2 + p];
            hs0[jp * 2 + p] = fmaf(u, o - h, h);
        }
        __syncthreads();

        // prefetch G for t+1
        float ngx0 = 0.f, ngx1 = 0.f, ngo = 0.f;
        if (t + 1 < SEQ) {
            const float* Gn = Gf + ((size_t)(t + 1) * BATCH + b0) * 384;
            ngx0 = Gn[j]; ngx1 = Gn[384 + j]; ngo = Gn[(size_t)p * 384 + 256 + jp];
        }

        // ---- stage 3: layer1 r,u. K=256 split: kh=0 -> h0-part, kh=1 -> h1-part ----
        a = 0ull;
        {
            const float* hsrc = kh ? hs1 : hs0;
            const ull*  wsrc = sW1ru + (kh ? 32 * 256 : 0);
            #pragma unroll
            for (int k4 = 0; k4 < 32; k4++) {
                float f0, f1, f2, f3;
                h4_to_f4(wsrc[k4 * 256 + j], f0, f1, f2, f3);
                ulonglong2 h01 = *(const ulonglong2*)&hsrc[k4 * 8];
                ulonglong2 h23 = *(const ulonglong2*)&hsrc[k4 * 8 + 4];
                a = fma2(h01.x, pack2(f0, f0), a);
                a = fma2(h01.y, pack2(f1, f1), a);
                a = fma2(h23.x, pack2(f2, f2), a);
                a = fma2(h23.y, pack2(f3, f3), a);
            }
        }
        if (kh) red1[j] = a;
        __syncthreads();
        if (!kh) {
            float v0, v1, w0, w1;
            unpack2(a, v0, v1); unpack2(red1[j], w0, w1);
            v0 = sigmoidf_(v0 + w0 + bias_ru); v1 = sigmoidf_(v1 + w1 + bias_ru);
            if (j < 128) {
                float2 h = *(const float2*)&hs1[j * 2];
                *(float2*)&rh[j * 2] = make_float2(v0 * h.x, v1 * h.y);
            } else {
                int jj = j - 128;
                us[jj] = v0; us[128 + jj] = v1;
            }
        }
        __syncthreads();

        // ---- stage 4: layer1 o + h1 update. K=256 split: kh=0 -> hs0, kh=1 -> rh ----
        acc = 0.f;
        {
            const float* hsrc = kh ? rh : hs0;
            const ull*  wsrc = g_Hq1o + (kh ? 32 * 128 : 0);
            #pragma unroll
            for (int k4 = 0; k4 < 32; k4++) {
                float f0, f1, f2, f3;
                h4_to_f4(wsrc[k4 * 128 + jp], f0, f1, f2, f3);
                const float* hv = &hsrc[k4 * 8 + p];
                acc = fmaf(hv[0], f0, acc);
                acc = fmaf(hv[2], f1, acc);
                acc = fmaf(hv[4], f2, acc);
                acc = fmaf(hv[6], f3, acc);
            }
        }
        if (kh) red2[p * 128 + jp] = acc;
        __syncthreads();
        if (!kh) {
            float o = tanhf(acc + red2[p * 128 + jp] + bias_o);
            float u = us[p * 128 + jp];
            float h = hs1[jp * 2 + p];
            hs1[jp * 2 + p] = fmaf(u, o - h, h);
        }
        __syncthreads();

        gx0 = ngx0; gx1 = ngx1; go = ngo;
    }
    for (int i = tid; i < HID * 2; i += 512)
        g_h1[(b0 + (i & 1)) * 128 + (i >> 1)] = hs1[i];
}

// ============ 4. classifier: out = h1 @ Wfc + bfc ============
__global__ __launch_bounds__(256) void fc_kernel(
    const float* __restrict__ Wfc, const float* __restrict__ bfc, float* __restrict__ out)
{
    __shared__ float h[4 * 128];
    const int tid = threadIdx.x, b0 = blockIdx.x * 4;
    for (int i = tid; i < 512; i += 256) h[i] = g_h1[(b0 + (i >> 7)) * 128 + (i & 127)];
    __syncthreads();
    const int n0 = blockIdx.y * 232;
    const int n1 = (n0 + 232 < NCLS) ? n0 + 232 : NCLS;
    for (int n = n0 + tid; n < n1; n += 256) {
        float a0 = 0.f, a1 = 0.f, a2 = 0.f, a3 = 0.f;
        #pragma unroll 4
        for (int k = 0; k < 128; k++) {
            float w = Wfc[k * NCLS + n];
            a0 = fmaf(h[k], w, a0);       a1 = fmaf(h[128 + k], w, a1);
            a2 = fmaf(h[256 + k], w, a2); a3 = fmaf(h[384 + k], w, a3);
        }
        float bb = bfc[n];
        out[(b0 + 0) * NCLS + n] = a0 + bb;
        out[(b0 + 1) * NCLS + n] = a1 + bb;
        out[(b0 + 2) * NCLS + n] = a2 + bb;
        out[(b0 + 3) * NCLS + n] = a3 + bb;
    }
}

extern "C" void kernel_launch(void* const* d_in, const int* in_sizes, int n_in,
                              void* d_out, int out_size)
{
    const float* X   = (const float*)d_in[0];
    const float* Wr0 = (const float*)d_in[1];  const float* br0 = (const float*)d_in[2];
    const float* Wu0 = (const float*)d_in[3];  const float* bu0 = (const float*)d_in[4];
    const float* Wo0 = (const float*)d_in[5];  const float* bo0 = (const float*)d_in[6];
    const float* Wr1 = (const float*)d_in[7];  const float* br1 = (const float*)d_in[8];
    const float* Wu1 = (const float*)d_in[9];  const float* bu1 = (const float*)d_in[10];
    const float* Wo1 = (const float*)d_in[11]; const float* bo1 = (const float*)d_in[12];
    const float* Wfc = (const float*)d_in[13]; const float* bfc = (const float*)d_in[14];
    float* out = (float*)d_out;

    const int rnn_smem = 24576 * 8;   // 192KB dynamic SMEM: fp16 W0ru | W1ru
    cudaFuncSetAttribute(rnn_kernel, cudaFuncAttributeMaxDynamicSharedMemorySize, rnn_smem);

    pack_kernel<<<(147456 + 255) / 256, 256>>>(Wr0, Wu0, Wo0, Wr1, Wu1, Wo1);
    gemm_x_kernel<<<dim3(6, 5, BATCH), 256>>>(X, Wr0, br0, Wu0, bu0, Wo0, bo0);
    rnn_kernel<<<128, 512, rnn_smem>>>(br1, bu1, bo1);
    fc_kernel<<<dim3(64, 8), 256>>>(Wfc, bfc, out);
}

// round 13
// speedup vs baseline: 2.5037x; 1.0511x over previous
#include <cuda_runtime.h>
#include <cuda_fp16.h>

#define HID   128
#define INCH  271
#define SEQ   281
#define NCLS  1854
#define BATCH 256

typedef unsigned long long ull;

__device__ __forceinline__ ull pack2(float lo, float hi) {
    ull r; asm("mov.b64 %0, {%1,%2};" : "=l"(r) : "f"(lo), "f"(hi)); return r;
}
__device__ __forceinline__ void unpack2(ull v, float& lo, float& hi) {
    asm("mov.b64 {%0,%1}, %2;" : "=f"(lo), "=f"(hi) : "l"(v));
}
__device__ __forceinline__ ull fma2(ull a, ull b, ull c) {
    ull d; asm("fma.rn.f32x2 %0, %1, %2, %3;" : "=l"(d) : "l"(a), "l"(b), "l"(c)); return d;
}
__device__ __forceinline__ float sigmoidf_(float x) {
    return __fdividef(1.0f, 1.0f + __expf(-x));
}
// split an 8-byte word of 4 halves into 4 floats
__device__ __forceinline__ void h4_to_f4(ull w, float& f0, float& f1, float& f2, float& f3) {
    __half2 h01 = *reinterpret_cast<__half2*>(&w);
    __half2 h23 = *(reinterpret_cast<__half2*>(&w) + 1);
    float2 a = __half22float2(h01), b = __half22float2(h23);
    f0 = a.x; f1 = a.y; f2 = b.x; f3 = b.y;
}

// -------- device scratch (static, no allocations) --------
__device__ float4 g_G4[(size_t)SEQ * BATCH * 96];   // G[t][b][384] pre-activations (fp32)
__device__ ull g_Hq0ru[32 * 256];                   // layer0 h-part r|u  (K=128,N=256)
__device__ ull g_Hq0o [32 * 128];                   // layer0 h-part o   (L2-streamed)
__device__ ull g_Hq1ru[64 * 256];                   // layer1 r|u         (K=256,N=256)
__device__ ull g_Hq1o [64 * 128];                   // layer1 o          (L2-streamed)
__device__ float g_h1[BATCH * HID];                 // final h1 [b][k]

// ============ 1. weight repack: fp32 [k][j] -> fp16 {[k4][j][kk]} ============
__global__ void pack_kernel(const float* __restrict__ Wr0, const float* __restrict__ Wu0,
                            const float* __restrict__ Wo0, const float* __restrict__ Wr1,
                            const float* __restrict__ Wu1, const float* __restrict__ Wo1)
{
    int i = blockIdx.x * blockDim.x + threadIdx.x;
    if (i < 32768) {
        int kk = i & 3, j = (i >> 2) & 255, k4 = i >> 10;
        const float* W = (j < 128) ? Wr0 : Wu0;
        ((__half*)g_Hq0ru)[i] = __float2half_rn(W[(271 + k4 * 4 + kk) * 128 + (j & 127)]);
    } else if (i < 49152) {
        int v = i - 32768, kk = v & 3, j = (v >> 2) & 127, k4 = v >> 9;
        ((__half*)g_Hq0o)[v] = __float2half_rn(Wo0[(271 + k4 * 4 + kk) * 128 + j]);
    } else if (i < 114688) {
        int v = i - 49152, kk = v & 3, j = (v >> 2) & 255, k4 = v >> 10;
        const float* W = (j < 128) ? Wr1 : Wu1;
        ((__half*)g_Hq1ru)[v] = __float2half_rn(W[(k4 * 4 + kk) * 128 + (j & 127)]);
    } else if (i < 147456) {
        int v = i - 114688, kk = v & 3, j = (v >> 2) & 127, k4 = v >> 9;
        ((__half*)g_Hq1o)[v] = __float2half_rn(Wo1[(k4 * 4 + kk) * 128 + j]);
    }
}

// ============ 2. G[t][b][j] = X[b,:,t] @ W0x[:,j] + bias (fp32) ============
__global__ __launch_bounds__(256) void gemm_x_kernel(
    const float* __restrict__ X,
    const float* __restrict__ Wr0, const float* __restrict__ br0,
    const float* __restrict__ Wu0, const float* __restrict__ bu0,
    const float* __restrict__ Wo0, const float* __restrict__ bo0)
{
    __shared__ __align__(16) float Xs[16 * 64];
    __shared__ __align__(16) float Ws[16 * 64];
    const int tid = threadIdx.x;
    const int jg0 = blockIdx.x * 64;
    const int t0  = blockIdx.y * 64;
    const int bz  = blockIdx.z;
    const int g   = jg0 >> 7;
    const float* Wsrc = (g == 0) ? Wr0 : (g == 1) ? Wu0 : Wo0;
    const float* bsrc = (g == 0) ? br0 : (g == 1) ? bu0 : bo0;
    const int jj0 = jg0 & 127;
    const int lr = tid >> 6, lc = tid & 63;
    const int ty = tid >> 4, tx = tid & 15;

    ull acc[4][2];
    #pragma unroll
    for (int m = 0; m < 4; m++) { acc[m][0] = 0ull; acc[m][1] = 0ull; }
    const float* Xb = X + (size_t)bz * (INCH * SEQ);

    for (int c0 = 0; c0 < INCH; c0 += 16) {
        #pragma unroll
        for (int i = 0; i < 4; i++) {
            int r = lr + 4 * i, c = c0 + r;
            float xv = 0.f, wv = 0.f;
            if (c < INCH) {
                int tcol = t0 + lc;
                if (tcol < SEQ) xv = Xb[c * SEQ + tcol];
                wv = Wsrc[c * 128 + jj0 + lc];
            }
            Xs[r * 64 + lc] = xv;
            Ws[r * 64 + lc] = wv;
        }
        __syncthreads();
        #pragma unroll
        for (int k = 0; k < 16; k++) {
            float4 a4 = *(const float4*)&Xs[k * 64 + ty * 4];
            ulonglong2 wv = *(const ulonglong2*)&Ws[k * 64 + tx * 4];
            const float* af = (const float*)&a4;
            #pragma unroll
            for (int m = 0; m < 4; m++) {
                ull ap = pack2(af[m], af[m]);
                acc[m][0] = fma2(ap, wv.x, acc[m][0]);
                acc[m][1] = fma2(ap, wv.y, acc[m][1]);
            }
        }
        __syncthreads();
    }
    float b0v = bsrc[jj0 + tx * 4 + 0], b1v = bsrc[jj0 + tx * 4 + 1];
    float b2v = bsrc[jj0 + tx * 4 + 2], b3v = bsrc[jj0 + tx * 4 + 3];
    float* Gf = (float*)g_G4;
    #pragma unroll
    for (int m = 0; m < 4; m++) {
        int tt = t0 + ty * 4 + m;
        if (tt < SEQ) {
            float o0, o1, o2, o3;
            unpack2(acc[m][0], o0, o1); unpack2(acc[m][1], o2, o3);
            *(float4*)&Gf[((size_t)tt * BATCH + bz) * 384 + jg0 + tx * 4] =
                make_float4(o0 + b0v, o1 + b1v, o2 + b2v, o3 + b3v);
        }
    }
}

// ============ 3. recurrence: 128 blocks x 2 batch rows, 1024 threads ============
// K-split x4: kq = tid>>8 takes a quarter of every stage's k-range; quarters
// reduce through SMEM. 32 warps/block = 8/SMSP for latency hiding.
// fp16 weights: W0ru + W1ru resident in 192KB dynamic SMEM; W0o/W1o from L2.
__global__ __launch_bounds__(1024) void rnn_kernel(
    const float* __restrict__ br1, const float* __restrict__ bu1,
    const float* __restrict__ bo1)
{
    extern __shared__ __align__(16) ull sW[];   // [0,8192) W0ru | [8192,24576) W1ru
    __shared__ __align__(8) float hs0[HID * 2];
    __shared__ __align__(8) float hs1[HID * 2];
    __shared__ __align__(8) float rh [HID * 2];
    __shared__ __align__(8) float us [2 * HID];
    __shared__ __align__(16) ull   red1[3 * 256];   // ru-stage partials (packed b-pair)
    __shared__ __align__(8)  float red2[3 * 256];   // o-stage partials

    const int tid = threadIdx.x;
    const int b0  = blockIdx.x * 2;
    const int j   = tid & 255;         // output column for ru stages
    const int kq  = tid >> 8;          // k-quarter selector (uniform per warp)
    const int jp  = tid & 127;
    const int p   = (tid >> 7) & 1;    // batch selector for o-gate stages

    for (int i = tid; i < 24576; i += 1024)
        sW[i] = (i < 8192) ? g_Hq0ru[i] : g_Hq1ru[i - 8192];
    for (int i = tid; i < HID * 2; i += 1024) { hs0[i] = 0.f; hs1[i] = 0.f; }
    __syncthreads();

    const float bias_ru = (j < 128) ? br1[j] : bu1[j - 128];
    const float bias_o  = bo1[jp];
    const float* Gf = (const float*)g_G4;
    const ull* sW1ru = sW + 8192;

    // G prefetch (only kq==0 threads consume gx/go)
    const float* Gt0 = Gf + (size_t)b0 * 384;
    float gx0 = Gt0[j];
    float gx1 = Gt0[384 + j];
    float go  = Gt0[(size_t)p * 384 + 256 + jp];

    for (int t = 0; t < SEQ; t++) {
        // ---- stage 1: layer0 r,u. thread=(j, kq), 8 k4 each ----
        ull a = 0ull;
        #pragma unroll
        for (int k4o = 0; k4o < 8; k4o++) {
            int k4 = kq * 8 + k4o;
            float f0, f1, f2, f3;
            h4_to_f4(sW[k4 * 256 + j], f0, f1, f2, f3);
            ulonglong2 h01 = *(const ulonglong2*)&hs0[k4 * 8];
            ulonglong2 h23 = *(const ulonglong2*)&hs0[k4 * 8 + 4];
            a = fma2(h01.x, pack2(f0, f0), a);
            a = fma2(h01.y, pack2(f1, f1), a);
            a = fma2(h23.x, pack2(f2, f2), a);
            a = fma2(h23.y, pack2(f3, f3), a);
        }
        if (kq) red1[(kq - 1) * 256 + j] = a;
        __syncthreads();
        if (!kq) {
            float v0, v1, w0, w1;
            unpack2(a, v0, v1);
            unpack2(red1[j], w0, w1);             v0 += w0; v1 += w1;
            unpack2(red1[256 + j], w0, w1);       v0 += w0; v1 += w1;
            unpack2(red1[512 + j], w0, w1);       v0 += w0; v1 += w1;
            v0 = sigmoidf_(v0 + gx0); v1 = sigmoidf_(v1 + gx1);
            if (j < 128) {
                float2 h = *(const float2*)&hs0[j * 2];
                *(float2*)&rh[j * 2] = make_float2(v0 * h.x, v1 * h.y);
            } else {
                int jj = j - 128;
                us[jj] = v0; us[128 + jj] = v1;
            }
        }
        __syncthreads();

        // ---- stage 2: layer0 o + h0 update. thread=(jp, p, kq), 8 k4 each ----
        float acc = 0.f;
        #pragma unroll
        for (int k4o = 0; k4o < 8; k4o++) {
            int k4 = kq * 8 + k4o;
            float f0, f1, f2, f3;
            h4_to_f4(g_Hq0o[k4 * 128 + jp], f0, f1, f2, f3);
            const float* hv = &rh[k4 * 8 + p];
            acc = fmaf(hv[0], f0, acc);
            acc = fmaf(hv[2], f1, acc);
            acc = fmaf(hv[4], f2, acc);
            acc = fmaf(hv[6], f3, acc);
        }
        if (kq) red2[(kq - 1) * 256 + p * 128 + jp] = acc;
        __syncthreads();
        if (!kq) {
            int ix = p * 128 + jp;
            acc += red2[ix] + red2[256 + ix] + red2[512 + ix];
            float o = tanhf(acc + go);
            float u = us[ix];
            float h = hs0[jp * 2 + p];
            hs0[jp * 2 + p] = fmaf(u, o - h, h);
        }
        __syncthreads();

        // prefetch G for t+1
        float ngx0 = 0.f, ngx1 = 0.f, ngo = 0.f;
        if (t + 1 < SEQ) {
            const float* Gn = Gf + ((size_t)(t + 1) * BATCH + b0) * 384;
            ngx0 = Gn[j]; ngx1 = Gn[384 + j]; ngo = Gn[(size_t)p * 384 + 256 + jp];
        }

        // ---- stage 3: layer1 r,u. K=256, 64 k4 total, 16 per quarter ----
        a = 0ull;
        {
            const float* hsrc = (kq < 2) ? hs0 : hs1;   // first 32 k4 -> h0, last 32 -> h1
            #pragma unroll
            for (int k4o = 0; k4o < 16; k4o++) {
                int k4g = kq * 16 + k4o;                // global k4 index 0..63
                int k4l = k4g & 31;                     // index within hsrc
                float f0, f1, f2, f3;
                h4_to_f4(sW1ru[k4g * 256 + j], f0, f1, f2, f3);
                ulonglong2 h01 = *(const ulonglong2*)&hsrc[k4l * 8];
                ulonglong2 h23 = *(const ulonglong2*)&hsrc[k4l * 8 + 4];
                a = fma2(h01.x, pack2(f0, f0), a);
                a = fma2(h01.y, pack2(f1, f1), a);
                a = fma2(h23.x, pack2(f2, f2), a);
                a = fma2(h23.y, pack2(f3, f3), a);
            }
        }
        if (kq) red1[(kq - 1) * 256 + j] = a;
        __syncthreads();
        if (!kq) {
            float v0, v1, w0, w1;
            unpack2(a, v0, v1);
            unpack2(red1[j], w0, w1);             v0 += w0; v1 += w1;
            unpack2(red1[256 + j], w0, w1);       v0 += w0; v1 += w1;
            unpack2(red1[512 + j], w0, w1);       v0 += w0; v1 += w1;
            v0 = sigmoidf_(v0 + bias_ru); v1 = sigmoidf_(v1 + bias_ru);
            if (j < 128) {
                float2 h = *(const float2*)&hs1[j * 2];
                *(float2*)&rh[j * 2] = make_float2(v0 * h.x, v1 * h.y);
            } else {
                int jj = j - 128;
                us[jj] = v0; us[128 + jj] = v1;
            }
        }
        __syncthreads();

        // ---- stage 4: layer1 o + h1 update. K=256, 64 k4 total, 16 per quarter ----
        acc = 0.f;
        {
            const float* hsrc = (kq < 2) ? hs0 : rh;    // first 32 k4 -> h0_new, last 32 -> r1*h1
            #pragma unroll
            for (int k4o = 0; k4o < 16; k4o++) {
                int k4g = kq * 16 + k4o;
                int k4l = k4g & 31;
                float f0, f1, f2, f3;
                h4_to_f4(g_Hq1o[k4g * 128 + jp], f0, f1, f2, f3);
                const float* hv = &hsrc[k4l * 8 + p];
                acc = fmaf(hv[0], f0, acc);
                acc = fmaf(hv[2], f1, acc);
                acc = fmaf(hv[4], f2, acc);
                acc = fmaf(hv[6], f3, acc);
            }
        }
        if (kq) red2[(kq - 1) * 256 + p * 128 + jp] = acc;
        __syncthreads();
        if (!kq) {
            int ix = p * 128 + jp;
            acc += red2[ix] + red2[256 + ix] + red2[512 + ix];
            float o = tanhf(acc + bias_o);
            float u = us[ix];
            float h = hs1[jp * 2 + p];
            hs1[jp * 2 + p] = fmaf(u, o - h, h);
        }
        __syncthreads();

        gx0 = ngx0; gx1 = ngx1; go = ngo;
    }
    for (int i = tid; i < HID * 2; i += 1024)
        g_h1[(b0 + (i & 1)) * 128 + (i >> 1)] = hs1[i];
}

// ============ 4. classifier: out = h1 @ Wfc + bfc ============
__global__ __launch_bounds__(256) void fc_kernel(
    const float* __restrict__ Wfc, const float* __restrict__ bfc, float* __restrict__ out)
{
    __shared__ float h[4 * 128];
    const int tid = threadIdx.x, b0 = blockIdx.x * 4;
    for (int i = tid; i < 512; i += 256) h[i] = g_h1[(b0 + (i >> 7)) * 128 + (i & 127)];
    __syncthreads();
    const int n0 = blockIdx.y * 232;
    const int n1 = (n0 + 232 < NCLS) ? n0 + 232 : NCLS;
    for (int n = n0 + tid; n < n1; n += 256) {
        float a0 = 0.f, a1 = 0.f, a2 = 0.f, a3 = 0.f;
        #pragma unroll 4
        for (int k = 0; k < 128; k++) {
            float w = Wfc[k * NCLS + n];
            a0 = fmaf(h[k], w, a0);       a1 = fmaf(h[128 + k], w, a1);
            a2 = fmaf(h[256 + k], w, a2); a3 = fmaf(h[384 + k], w, a3);
        }
        float bb = bfc[n];
        out[(b0 + 0) * NCLS + n] = a0 + bb;
        out[(b0 + 1) * NCLS + n] = a1 + bb;
        out[(b0 + 2) * NCLS + n] = a2 + bb;
        out[(b0 + 3) * NCLS + n] = a3 + bb;
    }
}

extern "C" void kernel_launch(void* const* d_in, const int* in_sizes, int n_in,
                              void* d_out, int out_size)
{
    const float* X   = (const float*)d_in[0];
    const float* Wr0 = (const float*)d_in[1];  const float* br0 = (const float*)d_in[2];
    const float* Wu0 = (const float*)d_in[3];  const float* bu0 = (const float*)d_in[4];
    const float* Wo0 = (const float*)d_in[5];  const float* bo0 = (const float*)d_in[6];
    const float* Wr1 = (const float*)d_in[7];  const float* br1 = (const float*)d_in[8];
    const float* Wu1 = (const float*)d_in[9];  const float* bu1 = (const float*)d_in[10];
    const float* Wo1 = (const float*)d_in[11]; const float* bo1 = (const float*)d_in[12];
    const float* Wfc = (const float*)d_in[13]; const float* bfc = (const float*)d_in[14];
    float* out = (float*)d_out;

    const int rnn_smem = 24576 * 8;   // 192KB dynamic SMEM: fp16 W0ru | W1ru
    cudaFuncSetAttribute(rnn_kernel, cudaFuncAttributeMaxDynamicSharedMemorySize, rnn_smem);

    pack_kernel<<<(147456 + 255) / 256, 256>>>(Wr0, Wu0, Wo0, Wr1, Wu1, Wo1);
    gemm_x_kernel<<<dim3(6, 5, BATCH), 256>>>(X, Wr0, br0, Wu0, bu0, Wo0, bo0);
    rnn_kernel<<<128, 1024, rnn_smem>>>(br1, bu1, bo1);
    fc_kernel<<<dim3(64, 8), 256>>>(Wfc, bfc, out);
}

// round 14
// speedup vs baseline: 2.6994x; 1.0782x over previous
#include <cuda_runtime.h>
#include <cuda_fp16.h>

#define HID   128
#define INCH  271
#define SEQ   281
#define NCLS  1854
#define BATCH 256

typedef unsigned long long ull;

__device__ __forceinline__ ull pack2(float lo, float hi) {
    ull r; asm("mov.b64 %0, {%1,%2};" : "=l"(r) : "f"(lo), "f"(hi)); return r;
}
__device__ __forceinline__ void unpack2(ull v, float& lo, float& hi) {
    asm("mov.b64 {%0,%1}, %2;" : "=f"(lo), "=f"(hi) : "l"(v));
}
__device__ __forceinline__ ull fma2(ull a, ull b, ull c) {
    ull d; asm("fma.rn.f32x2 %0, %1, %2, %3;" : "=l"(d) : "l"(a), "l"(b), "l"(c)); return d;
}
__device__ __forceinline__ ull addf2(ull a, ull b) {
    ull d; asm("add.rn.f32x2 %0, %1, %2;" : "=l"(d) : "l"(a), "l"(b)); return d;
}
__device__ __forceinline__ float sigmoidf_(float x) {
    return __fdividef(1.0f, 1.0f + __expf(-x));
}
__device__ __forceinline__ void h4_to_f4(ull w, float& f0, float& f1, float& f2, float& f3) {
    __half2 h01 = *reinterpret_cast<__half2*>(&w);
    __half2 h23 = *(reinterpret_cast<__half2*>(&w) + 1);
    float2 a = __half22float2(h01), b = __half22float2(h23);
    f0 = a.x; f1 = a.y; f2 = b.x; f3 = b.y;
}
#define BAR_A() asm volatile("bar.sync 1, 512;" ::: "memory")
#define BAR_B() asm volatile("bar.sync 2, 512;" ::: "memory")

// -------- device scratch --------
__device__ float4 g_G4[(size_t)SEQ * BATCH * 96];   // G[t][b][384] pre-activations (fp32)
__device__ ull g_Hq0ru[32 * 256];                   // layer0 h-part r|u  (SMEM-resident)
__device__ ull g_Hq0o [32 * 128];                   // layer0 h-part o   (L2-streamed)
__device__ ull g_Hq1ru[64 * 256];                   // layer1 r|u        (SMEM-resident)
__device__ ull g_Hq1o [64 * 128];                   // layer1 o          (L2-streamed)
__device__ float g_h1[BATCH * HID];                 // final h1 [b][k]

// ============ 1. weight repack ============
__global__ void pack_kernel(const float* __restrict__ Wr0, const float* __restrict__ Wu0,
                            const float* __restrict__ Wo0, const float* __restrict__ Wr1,
                            const float* __restrict__ Wu1, const float* __restrict__ Wo1)
{
    int i = blockIdx.x * blockDim.x + threadIdx.x;
    if (i < 32768) {
        int kk = i & 3, j = (i >> 2) & 255, k4 = i >> 10;
        const float* W = (j < 128) ? Wr0 : Wu0;
        ((__half*)g_Hq0ru)[i] = __float2half_rn(W[(271 + k4 * 4 + kk) * 128 + (j & 127)]);
    } else if (i < 49152) {
        int v = i - 32768, kk = v & 3, j = (v >> 2) & 127, k4 = v >> 9;
        ((__half*)g_Hq0o)[v] = __float2half_rn(Wo0[(271 + k4 * 4 + kk) * 128 + j]);
    } else if (i < 114688) {
        int v = i - 49152, kk = v & 3, j = (v >> 2) & 255, k4 = v >> 10;
        const float* W = (j < 128) ? Wr1 : Wu1;
        ((__half*)g_Hq1ru)[v] = __float2half_rn(W[(k4 * 4 + kk) * 128 + (j & 127)]);
    } else if (i < 147456) {
        int v = i - 114688, kk = v & 3, j = (v >> 2) & 127, k4 = v >> 9;
        ((__half*)g_Hq1o)[v] = __float2half_rn(Wo1[(k4 * 4 + kk) * 128 + j]);
    }
}

// ============ 2. G[t][b][j] = X[b,:,t] @ W0x[:,j] + bias (fp32) ============
__global__ __launch_bounds__(256) void gemm_x_kernel(
    const float* __restrict__ X,
    const float* __restrict__ Wr0, const float* __restrict__ br0,
    const float* __restrict__ Wu0, const float* __restrict__ bu0,
    const float* __restrict__ Wo0, const float* __restrict__ bo0)
{
    __shared__ __align__(16) float Xs[16 * 64];
    __shared__ __align__(16) float Ws[16 * 64];
    const int tid = threadIdx.x;
    const int jg0 = blockIdx.x * 64;
    const int t0  = blockIdx.y * 64;
    const int bz  = blockIdx.z;
    const int g   = jg0 >> 7;
    const float* Wsrc = (g == 0) ? Wr0 : (g == 1) ? Wu0 : Wo0;
    const float* bsrc = (g == 0) ? br0 : (g == 1) ? bu0 : bo0;
    const int jj0 = jg0 & 127;
    const int lr = tid >> 6, lc = tid & 63;
    const int ty = tid >> 4, tx = tid & 15;

    ull acc[4][2];
    #pragma unroll
    for (int m = 0; m < 4; m++) { acc[m][0] = 0ull; acc[m][1] = 0ull; }
    const float* Xb = X + (size_t)bz * (INCH * SEQ);

    for (int c0 = 0; c0 < INCH; c0 += 16) {
        #pragma unroll
        for (int i = 0; i < 4; i++) {
            int r = lr + 4 * i, c = c0 + r;
            float xv = 0.f, wv = 0.f;
            if (c < INCH) {
                int tcol = t0 + lc;
                if (tcol < SEQ) xv = Xb[c * SEQ + tcol];
                wv = Wsrc[c * 128 + jj0 + lc];
            }
            Xs[r * 64 + lc] = xv;
            Ws[r * 64 + lc] = wv;
        }
        __syncthreads();
        #pragma unroll
        for (int k = 0; k < 16; k++) {
            float4 a4 = *(const float4*)&Xs[k * 64 + ty * 4];
            ulonglong2 wv = *(const ulonglong2*)&Ws[k * 64 + tx * 4];
            const float* af = (const float*)&a4;
            #pragma unroll
            for (int m = 0; m < 4; m++) {
                ull ap = pack2(af[m], af[m]);
                acc[m][0] = fma2(ap, wv.x, acc[m][0]);
                acc[m][1] = fma2(ap, wv.y, acc[m][1]);
            }
        }
        __syncthreads();
    }
    float b0v = bsrc[jj0 + tx * 4 + 0], b1v = bsrc[jj0 + tx * 4 + 1];
    float b2v = bsrc[jj0 + tx * 4 + 2], b3v = bsrc[jj0 + tx * 4 + 3];
    float* Gf = (float*)g_G4;
    #pragma unroll
    for (int m = 0; m < 4; m++) {
        int tt = t0 + ty * 4 + m;
        if (tt < SEQ) {
            float o0, o1, o2, o3;
            unpack2(acc[m][0], o0, o1); unpack2(acc[m][1], o2, o3);
            *(float4*)&Gf[((size_t)tt * BATCH + bz) * 384 + jg0 + tx * 4] =
                make_float4(o0 + b0v, o1 + b1v, o2 + b2v, o3 + b3v);
        }
    }
}

// ============ 3. recurrence: warp-specialized layer pipeline ============
// 128 blocks x 2 batch rows x 1024 threads. Warps 0-15 (group A) compute
// layer0 at step i; warps 16-31 (group B) compute layer1 at step i-1.
// h0 handed through a 2-slot SMEM double buffer; one global bar per step.
__global__ __launch_bounds__(1024) void rnn_kernel(
    const float* __restrict__ br1, const float* __restrict__ bu1,
    const float* __restrict__ bo1)
{
    extern __shared__ __align__(16) ull sW[];   // [0,8192) W0ru | [8192,24576) W1ru
    __shared__ __align__(16) float h0buf[2][HID * 2];
    __shared__ __align__(16) float hs1[HID * 2];
    __shared__ __align__(16) float rhA[HID * 2], rhB[HID * 2];
    __shared__ __align__(8)  float usA[2 * HID], usB[2 * HID];
    __shared__ __align__(16) ull   redA[256], redB[256];
    __shared__ __align__(8)  float red2A[256], red2B[256];

    const int tid = threadIdx.x;
    const int b0  = blockIdx.x * 2;
    const bool isA = tid < 512;
    const int t2 = isA ? tid : tid - 512;
    const int j  = t2 & 255;
    const int kh = t2 >> 8;             // k-half (uniform per warp)
    const int jp = t2 & 127;
    const int p  = (t2 >> 7) & 1;

    for (int i = tid; i < 24576; i += 1024)
        sW[i] = (i < 8192) ? g_Hq0ru[i] : g_Hq1ru[i - 8192];
    for (int i = tid; i < HID * 2; i += 1024) {
        h0buf[0][i] = 0.f; h0buf[1][i] = 0.f; hs1[i] = 0.f;
    }
    __syncthreads();

    const float* Gf = (const float*)g_G4;
    const ull* sW1ru = sW + 8192;

    float bias_ru = 0.f, bias_o = 0.f;
    float gx0 = 0.f, gx1 = 0.f, go = 0.f;
    if (isA) {
        const float* Gt0 = Gf + (size_t)b0 * 384;
        gx0 = Gt0[j]; gx1 = Gt0[384 + j]; go = Gt0[(size_t)p * 384 + 256 + jp];
    } else {
        bias_ru = (j < 128) ? br1[j] : bu1[j - 128];
        bias_o  = bo1[jp];
    }

    for (int i = 0; i <= SEQ; i++) {
        if (isA) {
            if (i < SEQ) {
                const float* h0prev = h0buf[(i + 1) & 1];
                float ngx0 = 0.f, ngx1 = 0.f, ngo = 0.f;
                if (i + 1 < SEQ) {
                    const float* Gn = Gf + ((size_t)(i + 1) * BATCH + b0) * 384;
                    ngx0 = Gn[j]; ngx1 = Gn[384 + j]; ngo = Gn[(size_t)p * 384 + 256 + jp];
                }
                // -- s1: layer0 r,u --
                ull a = 0ull, a2 = 0ull;
                #pragma unroll
                for (int k4o = 0; k4o < 16; k4o += 2) {
                    int k4 = kh * 16 + k4o;
                    float f0, f1, f2, f3;
                    h4_to_f4(sW[k4 * 256 + j], f0, f1, f2, f3);
                    ulonglong2 h01 = *(const ulonglong2*)&h0prev[k4 * 8];
                    ulonglong2 h23 = *(const ulonglong2*)&h0prev[k4 * 8 + 4];
                    a = fma2(h01.x, pack2(f0, f0), a);
                    a = fma2(h01.y, pack2(f1, f1), a);
                    a = fma2(h23.x, pack2(f2, f2), a);
                    a = fma2(h23.y, pack2(f3, f3), a);
                    h4_to_f4(sW[(k4 + 1) * 256 + j], f0, f1, f2, f3);
                    h01 = *(const ulonglong2*)&h0prev[(k4 + 1) * 8];
                    h23 = *(const ulonglong2*)&h0prev[(k4 + 1) * 8 + 4];
                    a2 = fma2(h01.x, pack2(f0, f0), a2);
                    a2 = fma2(h01.y, pack2(f1, f1), a2);
                    a2 = fma2(h23.x, pack2(f2, f2), a2);
                    a2 = fma2(h23.y, pack2(f3, f3), a2);
                }
                a = addf2(a, a2);
                if (kh) redA[j] = a;
                BAR_A();
                if (!kh) {
                    float v0, v1, w0, w1;
                    unpack2(a, v0, v1); unpack2(redA[j], w0, w1);
                    v0 = sigmoidf_(v0 + w0 + gx0); v1 = sigmoidf_(v1 + w1 + gx1);
                    if (j < 128) {
                        rhA[j * 2]     = v0 * h0prev[j * 2];
                        rhA[j * 2 + 1] = v1 * h0prev[j * 2 + 1];
                    } else {
                        usA[j - 128] = v0; usA[j] = v1;
                    }
                }
                BAR_A();
                // -- s2: layer0 o + h0 update --
                float acc = 0.f, acc2 = 0.f;
                #pragma unroll
                for (int k4o = 0; k4o < 16; k4o += 2) {
                    int k4 = kh * 16 + k4o;
                    float f0, f1, f2, f3;
                    h4_to_f4(g_Hq0o[k4 * 128 + jp], f0, f1, f2, f3);
                    const float* hv = &rhA[k4 * 8 + p];
                    acc = fmaf(hv[0], f0, acc); acc = fmaf(hv[2], f1, acc);
                    acc = fmaf(hv[4], f2, acc); acc = fmaf(hv[6], f3, acc);
                    h4_to_f4(g_Hq0o[(k4 + 1) * 128 + jp], f0, f1, f2, f3);
                    const float* hw = &rhA[(k4 + 1) * 8 + p];
                    acc2 = fmaf(hw[0], f0, acc2); acc2 = fmaf(hw[2], f1, acc2);
                    acc2 = fmaf(hw[4], f2, acc2); acc2 = fmaf(hw[6], f3, acc2);
                }
                acc += acc2;
                if (kh) red2A[p * 128 + jp] = acc;
                BAR_A();
                if (!kh) {
                    int ix = p * 128 + jp;
                    float o = tanhf(acc + red2A[ix] + go);
                    float u = usA[ix];
                    float h = h0prev[jp * 2 + p];
                    h0buf[i & 1][jp * 2 + p] = fmaf(u, o - h, h);
                }
                gx0 = ngx0; gx1 = ngx1; go = ngo;
            }
        } else {
            if (i >= 1) {
                const float* h0m = h0buf[(i - 1) & 1];
                // -- s3: layer1 r,u (K=256 split by kh) --
                ull a = 0ull, a2 = 0ull;
                const float* hsrc = kh ? hs1 : h0m;
                const ull* wsrc = sW1ru + kh * 32 * 256;
                #pragma unroll
                for (int k4 = 0; k4 < 32; k4 += 2) {
                    float f0, f1, f2, f3;
                    h4_to_f4(wsrc[k4 * 256 + j], f0, f1, f2, f3);
                    ulonglong2 h01 = *(const ulonglong2*)&hsrc[k4 * 8];
                    ulonglong2 h23 = *(const ulonglong2*)&hsrc[k4 * 8 + 4];
                    a = fma2(h01.x, pack2(f0, f0), a);
                    a = fma2(h01.y, pack2(f1, f1), a);
                    a = fma2(h23.x, pack2(f2, f2), a);
                    a = fma2(h23.y, pack2(f3, f3), a);
                    h4_to_f4(wsrc[(k4 + 1) * 256 + j], f0, f1, f2, f3);
                    h01 = *(const ulonglong2*)&hsrc[(k4 + 1) * 8];
                    h23 = *(const ulonglong2*)&hsrc[(k4 + 1) * 8 + 4];
                    a2 = fma2(h01.x, pack2(f0, f0), a2);
                    a2 = fma2(h01.y, pack2(f1, f1), a2);
                    a2 = fma2(h23.x, pack2(f2, f2), a2);
                    a2 = fma2(h23.y, pack2(f3, f3), a2);
                }
                a = addf2(a, a2);
                if (kh) redB[j] = a;
                BAR_B();
                if (!kh) {
                    float v0, v1, w0, w1;
                    unpack2(a, v0, v1); unpack2(redB[j], w0, w1);
                    v0 = sigmoidf_(v0 + w0 + bias_ru); v1 = sigmoidf_(v1 + w1 + bias_ru);
                    if (j < 128) {
                        rhB[j * 2]     = v0 * hs1[j * 2];
                        rhB[j * 2 + 1] = v1 * hs1[j * 2 + 1];
                    } else {
                        usB[j - 128] = v0; usB[j] = v1;
                    }
                }
                BAR_B();
                // -- s4: layer1 o + h1 update --
                float acc = 0.f, acc2 = 0.f;
                const float* hsrc4 = kh ? rhB : h0m;
                const ull* wsrc4 = g_Hq1o + kh * 32 * 128;
                #pragma unroll
                for (int k4 = 0; k4 < 32; k4 += 2) {
                    float f0, f1, f2, f3;
                    h4_to_f4(wsrc4[k4 * 128 + jp], f0, f1, f2, f3);
                    const float* hv = &hsrc4[k4 * 8 + p];
                    acc = fmaf(hv[0], f0, acc); acc = fmaf(hv[2], f1, acc);
                    acc = fmaf(hv[4], f2, acc); acc = fmaf(hv[6], f3, acc);
                    h4_to_f4(wsrc4[(k4 + 1) * 128 + jp], f0, f1, f2, f3);
                    const float* hw = &hsrc4[(k4 + 1) * 8 + p];
                    acc2 = fmaf(hw[0], f0, acc2); acc2 = fmaf(hw[2], f1, acc2);
                    acc2 = fmaf(hw[4], f2, acc2); acc2 = fmaf(hw[6], f3, acc2);
                }
                acc += acc2;
                if (kh) red2B[p * 128 + jp] = acc;
                BAR_B();
                if (!kh) {
                    int ix = p * 128 + jp;
                    float o = tanhf(acc + red2B[ix] + bias_o);
                    float u = usB[ix];
                    float h = hs1[jp * 2 + p];
                    hs1[jp * 2 + p] = fmaf(u, o - h, h);
                }
            }
        }
        __syncthreads();
    }
    if (!isA) {
        for (int i2 = t2; i2 < HID * 2; i2 += 512)
            g_h1[(b0 + (i2 & 1)) * 128 + (i2 >> 1)] = hs1[i2];
    }
}

// ============ 4. classifier: out = h1 @ Wfc + bfc ============
__global__ __launch_bounds__(256) void fc_kernel(
    const float* __restrict__ Wfc, const float* __restrict__ bfc, float* __restrict__ out)
{
    __shared__ float h[4 * 128];
    const int tid = threadIdx.x, b0 = blockIdx.x * 4;
    for (int i = tid; i < 512; i += 256) h[i] = g_h1[(b0 + (i >> 7)) * 128 + (i & 127)];
    __syncthreads();
    const int n0 = blockIdx.y * 232;
    const int n1 = (n0 + 232 < NCLS) ? n0 + 232 : NCLS;
    for (int n = n0 + tid; n < n1; n += 256) {
        float a0 = 0.f, a1 = 0.f, a2 = 0.f, a3 = 0.f;
        #pragma unroll 4
        for (int k = 0; k < 128; k++) {
            float w = Wfc[k * NCLS + n];
            a0 = fmaf(h[k], w, a0);       a1 = fmaf(h[128 + k], w, a1);
            a2 = fmaf(h[256 + k], w, a2); a3 = fmaf(h[384 + k], w, a3);
        }
        float bb = bfc[n];
        out[(b0 + 0) * NCLS + n] = a0 + bb;
        out[(b0 + 1) * NCLS + n] = a1 + bb;
        out[(b0 + 2) * NCLS + n] = a2 + bb;
        out[(b0 + 3) * NCLS + n] = a3 + bb;
    }
}

extern "C" void kernel_launch(void* const* d_in, const int* in_sizes, int n_in,
                              void* d_out, int out_size)
{
    const float* X   = (const float*)d_in[0];
    const float* Wr0 = (const float*)d_in[1];  const float* br0 = (const float*)d_in[2];
    const float* Wu0 = (const float*)d_in[3];  const float* bu0 = (const float*)d_in[4];
    const float* Wo0 = (const float*)d_in[5];  const float* bo0 = (const float*)d_in[6];
    const float* Wr1 = (const float*)d_in[7];  const float* br1 = (const float*)d_in[8];
    const float* Wu1 = (const float*)d_in[9];  const float* bu1 = (const float*)d_in[10];
    const float* Wo1 = (const float*)d_in[11]; const float* bo1 = (const float*)d_in[12];
    const float* Wfc = (const float*)d_in[13]; const float* bfc = (const float*)d_in[14];
    float* out = (float*)d_out;

    const int rnn_smem = 24576 * 8;   // 192KB dynamic SMEM: fp16 W0ru | W1ru
    cudaFuncSetAttribute(rnn_kernel, cudaFuncAttributeMaxDynamicSharedMemorySize, rnn_smem);

    pack_kernel<<<(147456 + 255) / 256, 256>>>(Wr0, Wu0, Wo0, Wr1, Wu1, Wo1);
    gemm_x_kernel<<<dim3(6, 5, BATCH), 256>>>(X, Wr0, br0, Wu0, bu0, Wo0, bo0);
    rnn_kernel<<<128, 1024, rnn_smem>>>(br1, bu1, bo1);
    fc_kernel<<<dim3(64, 8), 256>>>(Wfc, bfc, out);
}